// round 3
// baseline (speedup 1.0000x reference)
#include <cuda_runtime.h>

#define Bdim 4
#define Ndim 512
#define NCdim 128
#define ECdim 32
#define OCdim 64
#define KNdim 10
#define KEdim 5
#define NIN 192   // 2*EC + NC

// node-level scratch (no alloc allowed)
__device__ float g_n1[Bdim*Ndim*OCdim];
__device__ float g_n2[Bdim*Ndim*OCdim];
__device__ float g_q1[Bdim*Ndim*OCdim];
__device__ float g_q2[Bdim*Ndim*OCdim];

__device__ __forceinline__ float silu_f(float x) {
    return x * (1.0f / (1.0f + __expf(-x)));
}

// ---------------------------------------------------------------------------
// Kernel 1: per-node work. One block per (b, i). 256 threads.
// ---------------------------------------------------------------------------
__global__ __launch_bounds__(256)
void node_kernel(const float* __restrict__ node,
                 const float* __restrict__ edge,
                 const int* __restrict__ block_id,
                 const int* __restrict__ vmask,       // int32 OR float32 bits; !=0 test
                 const float* __restrict__ W_nt, const float* __restrict__ b_nt,
                 const float* __restrict__ W_n1, const float* __restrict__ b_n1,
                 const float* __restrict__ W_f1,
                 const float* __restrict__ W_no1, const float* __restrict__ b_no1,
                 const float* __restrict__ g_no, const float* __restrict__ be_no,
                 const float* __restrict__ W_no2, const float* __restrict__ b_no2,
                 float* __restrict__ out_node)
{
    const int bi = blockIdx.x;
    const int b  = bi / Ndim;
    const int i  = bi % Ndim;
    const int tid = threadIdx.x;

    __shared__ int           s_bid[Ndim];
    __shared__ unsigned char s_vm[Ndim];
    __shared__ float s_inp[NIN];
    __shared__ float s_red[8][64];
    __shared__ float s_cnt[2][8];
    __shared__ float s_h[NCdim];
    __shared__ float s_n[NCdim];
    __shared__ float s_t[NCdim];
    __shared__ float s_v[NCdim];
    __shared__ float s_stat[2];

    for (int k = tid; k < Ndim; k += 256) {
        s_bid[k] = block_id[b*Ndim + k];
        s_vm[k]  = (vmask[b*Ndim + k] != 0) ? 1 : 0;
    }
    __syncthreads();

    const int  bii  = s_bid[i];
    const bool nm_i = (bii >= 0);
    const bool vm_i = (s_vm[i] != 0);

    const int c  = tid & 31;
    const int jl = tid >> 5;   // 0..7, uniform per warp

    float acc_in = 0.f, acc_out = 0.f, cnt_in = 0.f, cnt_out = 0.f;
    const float* erow = edge + ((size_t)(b*Ndim + i) * Ndim) * ECdim;             // edge[b,i,j,:]
    const float* ecol = edge + ((size_t)b*Ndim) * Ndim * ECdim + (size_t)i*ECdim; // edge[b,j,i,:]

    for (int j = jl; j < Ndim; j += 8) {
        int  bj   = s_bid[j];
        bool nm_j = (bj >= 0);
        bool pv   = nm_i && nm_j;
        bool cij  = pv && ((bii > bj) || (bii == bj && !vm_i));
        bool cji  = pv && ((bj > bii) || (bj == bii && (s_vm[j] == 0)));
        if (cij) { acc_in  += erow[(size_t)j*ECdim + c];        cnt_in  += 1.f; }
        if (cji) { acc_out += ecol[(size_t)j*Ndim*ECdim + c];   cnt_out += 1.f; }
    }
    s_red[jl][c]      = acc_in;
    s_red[jl][c + 32] = acc_out;
    if (c == 0) { s_cnt[0][jl] = cnt_in; s_cnt[1][jl] = cnt_out; }
    __syncthreads();

    if (tid < 64) {
        float s = 0.f, cnt = 0.f;
        #pragma unroll
        for (int r = 0; r < 8; r++) { s += s_red[r][tid]; cnt += s_cnt[tid >> 5][r]; }
        s_inp[tid] = s / fmaxf(cnt, 1.f);
    }
    if (tid >= 64 && tid < NIN) {
        float nd = node[(size_t)(b*Ndim + i)*NCdim + (tid - 64)];
        s_inp[tid] = nm_i ? nd : 0.f;
    }
    __syncthreads();

    // h = silu([x_in,x_out,nodem] @ W_nt + b_nt) * nm
    if (tid < NCdim) {
        float a = b_nt[tid];
        #pragma unroll 4
        for (int k = 0; k < NIN; k++) a += s_inp[k] * W_nt[k*NCdim + tid];
        s_h[tid] = nm_i ? silu_f(a) : 0.f;
    }
    __syncthreads();

    // n = h @ W_n1 + b_n1
    if (tid < NCdim) {
        float a = b_n1[tid];
        #pragma unroll 4
        for (int k = 0; k < NCdim; k++) a += s_h[k] * W_n1[k*NCdim + tid];
        s_n[tid] = a;
    }
    __syncthreads();
    // t = h @ W_no1 + b_no1 (node logit branch)
    if (tid < NCdim) {
        float a = b_no1[tid];
        #pragma unroll 4
        for (int k = 0; k < NCdim; k++) a += s_h[k] * W_no1[k*NCdim + tid];
        s_t[tid] = a;
    }
    __syncthreads();

    // q1 = n1 @ W_f1, q2 = n2 @ W_f1 (bias added later, once, on the edge side)
    if (tid < 2*OCdim) {
        const int which = tid >> 6;   // 0 -> q1 (from n1), 1 -> q2 (from n2)
        const int o = tid & 63;
        const float* src = s_n + which*OCdim;
        float a = 0.f;
        #pragma unroll 4
        for (int k = 0; k < OCdim; k++) a += src[k] * W_f1[k*OCdim + o];
        size_t off = (size_t)(b*Ndim + i)*OCdim + o;
        if (which == 0) { g_q1[off] = a; g_n1[off] = s_n[o]; }
        else            { g_q2[off] = a; g_n2[off] = s_n[OCdim + o]; }
    }

    // LayerNorm over 128 of s_t
    if (tid < 32) {
        float s = s_t[tid] + s_t[tid+32] + s_t[tid+64] + s_t[tid+96];
        #pragma unroll
        for (int o = 16; o; o >>= 1) s += __shfl_down_sync(0xffffffffu, s, o);
        if (tid == 0) s_stat[0] = s * (1.f/NCdim);
    }
    __syncthreads();
    const float mean = s_stat[0];
    if (tid < 32) {
        float s = 0.f;
        #pragma unroll
        for (int r = 0; r < 4; r++) { float d = s_t[tid + 32*r] - mean; s += d*d; }
        #pragma unroll
        for (int o = 16; o; o >>= 1) s += __shfl_down_sync(0xffffffffu, s, o);
        if (tid == 0) s_stat[1] = rsqrtf(s * (1.f/NCdim) + 1e-5f);
    }
    __syncthreads();
    if (tid < NCdim)
        s_v[tid] = silu_f((s_t[tid] - mean) * s_stat[1] * g_no[tid] + be_no[tid]);
    __syncthreads();
    if (tid < KNdim) {
        float a = b_no2[tid];
        #pragma unroll 4
        for (int k = 0; k < NCdim; k++) a += s_v[k] * W_no2[k*KNdim + tid];
        out_node[(size_t)(b*Ndim + i)*KNdim + tid] = nm_i ? a : 0.f;
    }
}

// ---------------------------------------------------------------------------
// Kernel 2: edge work on unordered pairs. Block = 256 threads = 4 groups of 64.
// ---------------------------------------------------------------------------
__global__ __launch_bounds__(256, 1)
void edge_kernel(const float* __restrict__ edge,
                 const int* __restrict__ block_id,
                 const int* __restrict__ vmask,
                 const float* __restrict__ W_e1, const float* __restrict__ b_e1,
                 const float* __restrict__ b_f1,
                 const float* __restrict__ W_f2, const float* __restrict__ b_f2,
                 const float* __restrict__ W_eo1, const float* __restrict__ b_eo1,
                 const float* __restrict__ g_eo, const float* __restrict__ be_eo,
                 const float* __restrict__ W_eo2, const float* __restrict__ b_eo2,
                 float* __restrict__ out_edge)
{
    const int b = blockIdx.x >> 8;
    const int r = blockIdx.x & 255;
    const int tid = threadIdx.x;
    const int g = tid >> 6;
    const int c = tid & 63;

    __shared__ int           s_bid[Ndim];
    __shared__ unsigned char s_vm[Ndim];
    __shared__ float s_weo1[OCdim*32];
    __shared__ float s_weo2[32*KEdim];
    __shared__ float s_beo1[32], s_geo[32], s_beeo[32], s_beo2[KEdim];
    __shared__ __align__(16) float s_er[4][2][ECdim];
    __shared__ __align__(16) float s_e1[4][2][OCdim];
    __shared__ __align__(16) float s_es[4][OCdim];
    __shared__ float s_u[4][2][32];
    __shared__ float s_v[4][32];

    for (int k = tid; k < Ndim; k += 256) {
        s_bid[k] = block_id[b*Ndim + k];
        s_vm[k]  = (vmask[b*Ndim + k] != 0) ? 1 : 0;
    }
    for (int k = tid; k < OCdim*32; k += 256) s_weo1[k] = W_eo1[k];
    if (tid < 32*KEdim) s_weo2[tid] = W_eo2[tid];
    if (tid < 32) { s_beo1[tid] = b_eo1[tid]; s_geo[tid] = g_eo[tid]; s_beeo[tid] = be_eo[tid]; }
    if (tid < KEdim) s_beo2[tid] = b_eo2[tid];

    // weight columns in registers (amortized over ~513 pairs)
    float wE1[ECdim], wF2[OCdim];
    #pragma unroll
    for (int k = 0; k < ECdim; k++) wE1[k] = W_e1[k*OCdim + c];
    #pragma unroll
    for (int k = 0; k < OCdim; k++) wF2[k] = W_f2[k*OCdim + c];
    const float bE1c = b_e1[c];
    const float bF1c = b_f1[c];
    const float bF2c = b_f2[c];
    __syncthreads();

    const int i_a = r, i_b = Ndim - 1 - r;
    const int npairs_a = Ndim - i_a;
    const int total = npairs_a + (Ndim - i_b);   // == 513
    const int iters = (total + 3) >> 2;

    for (int it = 0; it < iters; it++) {
        const int p = it*4 + g;
        const bool active = (p < total);
        int i, j;
        if (p < npairs_a)      { i = i_a; j = i_a + p; }
        else if (active)       { i = i_b; j = i_b + (p - npairs_a); }
        else                   { i = i_a; j = i_a; }

        const int  bii = s_bid[i], bjj = s_bid[j];
        const bool nm2 = (bii >= 0) && (bjj >= 0);
        const bool cij = nm2 && ((bii > bjj) || (bii == bjj && s_vm[i] == 0));
        const bool cji = nm2 && ((bjj > bii) || (bjj == bii && s_vm[j] == 0));
        const float em = (cij || cji) ? 1.f : 0.f;

        // load raw edge vectors, pre-masked by em
        {
            const int cc = c & 31;
            const float* src = (c < 32)
                ? edge + ((size_t)(b*Ndim + i)*Ndim + j)*ECdim + cc
                : edge + ((size_t)(b*Ndim + j)*Ndim + i)*ECdim + cc;
            s_er[g][c >> 5][cc] = (*src) * em;
        }
        __syncthreads();

        // e1 = er @ W_e1 + b_e1 (both directions)
        float a_ij = bE1c, a_ji = bE1c;
        {
            const float4* er0 = (const float4*)s_er[g][0];
            const float4* er1 = (const float4*)s_er[g][1];
            #pragma unroll
            for (int k = 0; k < ECdim/4; k++) {
                float4 t0 = er0[k], t1 = er1[k];
                a_ij += t0.x*wE1[4*k] + t0.y*wE1[4*k+1] + t0.z*wE1[4*k+2] + t0.w*wE1[4*k+3];
                a_ji += t1.x*wE1[4*k] + t1.y*wE1[4*k+1] + t1.z*wE1[4*k+2] + t1.w*wE1[4*k+3];
            }
        }
        s_e1[g][0][c] = a_ij;
        s_e1[g][1][c] = a_ji;
        __syncthreads();

        // f2 = silu(e1 @ W_f2 + b_f2) (both directions)
        float f_ij = bF2c, f_ji = bF2c;
        {
            const float4* e10 = (const float4*)s_e1[g][0];
            const float4* e11 = (const float4*)s_e1[g][1];
            #pragma unroll
            for (int k = 0; k < OCdim/4; k++) {
                float4 t0 = e10[k], t1 = e11[k];
                f_ij += t0.x*wF2[4*k] + t0.y*wF2[4*k+1] + t0.z*wF2[4*k+2] + t0.w*wF2[4*k+3];
                f_ji += t1.x*wF2[4*k] + t1.y*wF2[4*k+1] + t1.z*wF2[4*k+2] + t1.w*wF2[4*k+3];
            }
        }
        f_ij = silu_f(f_ij);
        f_ji = silu_f(f_ji);

        // node-pair terms
        const size_t offi = (size_t)(b*Ndim + i)*OCdim + c;
        const size_t offj = (size_t)(b*Ndim + j)*OCdim + c;
        const float n1i = g_n1[offi], n1j = g_n1[offj];
        const float n2i = g_n2[offi], n2j = g_n2[offj];
        const float q1i = g_q1[offi], q1j = g_q1[offj];
        const float q2i = g_q2[offi], q2j = g_q2[offj];
        const float f1_ij = silu_f(q1j + q2i + bF1c);
        const float f1_ji = silu_f(q1i + q2j + bF1c);
        const float E_ij = silu_f(n1j + n2i + a_ij + f1_ij*f_ij);
        const float E_ji = silu_f(n1i + n2j + a_ji + f1_ji*f_ji);
        s_es[g][c] = (E_ij + E_ji) * em;
        __syncthreads();

        // u = es @ W_eo1 + b_eo1 : split k over thread halves
        {
            const int o  = c & 31;
            const int kh = (c >> 5) * 32;
            float u = 0.f;
            const float4* esv = (const float4*)(s_es[g] + kh);
            #pragma unroll
            for (int k = 0; k < 8; k++) {
                float4 t = esv[k];
                u += t.x*s_weo1[(kh+4*k  )*32 + o] + t.y*s_weo1[(kh+4*k+1)*32 + o]
                   + t.z*s_weo1[(kh+4*k+2)*32 + o] + t.w*s_weo1[(kh+4*k+3)*32 + o];
            }
            s_u[g][c >> 5][o] = u + ((c < 32) ? s_beo1[o] : 0.f);
        }
        __syncthreads();

        // LayerNorm over 32 + silu (threads 0..31 of group = one full warp)
        if (c < 32) {
            const float uu = s_u[g][0][c] + s_u[g][1][c];
            float m = uu;
            #pragma unroll
            for (int o2 = 16; o2; o2 >>= 1) m += __shfl_xor_sync(0xffffffffu, m, o2);
            m *= (1.f/32.f);
            const float d = uu - m;
            float var = d*d;
            #pragma unroll
            for (int o2 = 16; o2; o2 >>= 1) var += __shfl_xor_sync(0xffffffffu, var, o2);
            var *= (1.f/32.f);
            s_v[g][c] = silu_f(d * rsqrtf(var + 1e-5f) * s_geo[c] + s_beeo[c]);
        }
        __syncthreads();

        // logits = v @ W_eo2 + b_eo2, masked, written to (i,j) and (j,i)
        if (c < KEdim && active) {
            float a = s_beo2[c];
            #pragma unroll
            for (int k = 0; k < 32; k++) a += s_v[g][k] * s_weo2[k*KEdim + c];
            a *= em;
            out_edge[((size_t)(b*Ndim + i)*Ndim + j)*KEdim + c] = a;
            out_edge[((size_t)(b*Ndim + j)*Ndim + i)*KEdim + c] = a;
        }
        __syncthreads();
    }
}

// ---------------------------------------------------------------------------
extern "C" void kernel_launch(void* const* d_in, const int* in_sizes, int n_in,
                              void* d_out, int out_size)
{
    const float* node      = (const float*)d_in[0];
    const float* edge      = (const float*)d_in[1];
    const int*   block_id  = (const int*)d_in[2];
    const int*   vmask     = (const int*)d_in[3];
    const float* W_nt  = (const float*)d_in[4];
    const float* b_nt  = (const float*)d_in[5];
    const float* W_n1  = (const float*)d_in[6];
    const float* b_n1  = (const float*)d_in[7];
    const float* W_e1  = (const float*)d_in[8];
    const float* b_e1  = (const float*)d_in[9];
    const float* W_f1  = (const float*)d_in[10];
    const float* b_f1  = (const float*)d_in[11];
    const float* W_f2  = (const float*)d_in[12];
    const float* b_f2  = (const float*)d_in[13];
    const float* W_no1 = (const float*)d_in[14];
    const float* b_no1 = (const float*)d_in[15];
    const float* g_no  = (const float*)d_in[16];
    const float* be_no = (const float*)d_in[17];
    const float* W_no2 = (const float*)d_in[18];
    const float* b_no2 = (const float*)d_in[19];
    const float* W_eo1 = (const float*)d_in[20];
    const float* b_eo1 = (const float*)d_in[21];
    const float* g_eo  = (const float*)d_in[22];
    const float* be_eo = (const float*)d_in[23];
    const float* W_eo2 = (const float*)d_in[24];
    const float* b_eo2 = (const float*)d_in[25];

    float* out_node = (float*)d_out;                       // (B,N,KN)
    float* out_edge = (float*)d_out + Bdim*Ndim*KNdim;     // (B,N,N,KE)

    node_kernel<<<Bdim*Ndim, 256>>>(node, edge, block_id, vmask,
                                    W_nt, b_nt, W_n1, b_n1, W_f1,
                                    W_no1, b_no1, g_no, be_no, W_no2, b_no2,
                                    out_node);

    edge_kernel<<<Bdim*256, 256>>>(edge, block_id, vmask,
                                   W_e1, b_e1, b_f1, W_f2, b_f2,
                                   W_eo1, b_eo1, g_eo, be_eo, W_eo2, b_eo2,
                                   out_edge);
}

// round 4
// speedup vs baseline: 2.4333x; 2.4333x over previous
#include <cuda_runtime.h>

#define Bdim 4
#define Ndim 512
#define NCdim 128
#define ECdim 32
#define OCdim 64
#define KNdim 10
#define KEdim 5
#define NIN 192   // 2*EC + NC
#define EWARPS 8

// node-level scratch (no alloc allowed)
__device__ float g_n1[Bdim*Ndim*OCdim];
__device__ float g_n2[Bdim*Ndim*OCdim];
__device__ float g_q1[Bdim*Ndim*OCdim];
__device__ float g_q2[Bdim*Ndim*OCdim];

__device__ __forceinline__ float silu_f(float x) {
    return __fdividef(x, 1.0f + __expf(-x));
}
__device__ __forceinline__ float2 silu2(float2 x) {
    return make_float2(silu_f(x.x), silu_f(x.y));
}

// ---------------------------------------------------------------------------
// Kernel 1: per-node work. One block per (b, i). 256 threads. (unchanged)
// ---------------------------------------------------------------------------
__global__ __launch_bounds__(256)
void node_kernel(const float* __restrict__ node,
                 const float* __restrict__ edge,
                 const int* __restrict__ block_id,
                 const int* __restrict__ vmask,
                 const float* __restrict__ W_nt, const float* __restrict__ b_nt,
                 const float* __restrict__ W_n1, const float* __restrict__ b_n1,
                 const float* __restrict__ W_f1,
                 const float* __restrict__ W_no1, const float* __restrict__ b_no1,
                 const float* __restrict__ g_no, const float* __restrict__ be_no,
                 const float* __restrict__ W_no2, const float* __restrict__ b_no2,
                 float* __restrict__ out_node)
{
    const int bi = blockIdx.x;
    const int b  = bi / Ndim;
    const int i  = bi % Ndim;
    const int tid = threadIdx.x;

    __shared__ int           s_bid[Ndim];
    __shared__ unsigned char s_vm[Ndim];
    __shared__ float s_inp[NIN];
    __shared__ float s_red[8][64];
    __shared__ float s_cnt[2][8];
    __shared__ float s_h[NCdim];
    __shared__ float s_n[NCdim];
    __shared__ float s_t[NCdim];
    __shared__ float s_v[NCdim];
    __shared__ float s_stat[2];

    for (int k = tid; k < Ndim; k += 256) {
        s_bid[k] = block_id[b*Ndim + k];
        s_vm[k]  = (vmask[b*Ndim + k] != 0) ? 1 : 0;
    }
    __syncthreads();

    const int  bii  = s_bid[i];
    const bool nm_i = (bii >= 0);
    const bool vm_i = (s_vm[i] != 0);

    const int c  = tid & 31;
    const int jl = tid >> 5;

    float acc_in = 0.f, acc_out = 0.f, cnt_in = 0.f, cnt_out = 0.f;
    const float* erow = edge + ((size_t)(b*Ndim + i) * Ndim) * ECdim;
    const float* ecol = edge + ((size_t)b*Ndim) * Ndim * ECdim + (size_t)i*ECdim;

    for (int j = jl; j < Ndim; j += 8) {
        int  bj   = s_bid[j];
        bool nm_j = (bj >= 0);
        bool pv   = nm_i && nm_j;
        bool cij  = pv && ((bii > bj) || (bii == bj && !vm_i));
        bool cji  = pv && ((bj > bii) || (bj == bii && (s_vm[j] == 0)));
        if (cij) { acc_in  += erow[(size_t)j*ECdim + c];        cnt_in  += 1.f; }
        if (cji) { acc_out += ecol[(size_t)j*Ndim*ECdim + c];   cnt_out += 1.f; }
    }
    s_red[jl][c]      = acc_in;
    s_red[jl][c + 32] = acc_out;
    if (c == 0) { s_cnt[0][jl] = cnt_in; s_cnt[1][jl] = cnt_out; }
    __syncthreads();

    if (tid < 64) {
        float s = 0.f, cnt = 0.f;
        #pragma unroll
        for (int r = 0; r < 8; r++) { s += s_red[r][tid]; cnt += s_cnt[tid >> 5][r]; }
        s_inp[tid] = s / fmaxf(cnt, 1.f);
    }
    if (tid >= 64 && tid < NIN) {
        float nd = node[(size_t)(b*Ndim + i)*NCdim + (tid - 64)];
        s_inp[tid] = nm_i ? nd : 0.f;
    }
    __syncthreads();

    if (tid < NCdim) {
        float a = b_nt[tid];
        #pragma unroll 4
        for (int k = 0; k < NIN; k++) a += s_inp[k] * W_nt[k*NCdim + tid];
        s_h[tid] = nm_i ? silu_f(a) : 0.f;
    }
    __syncthreads();

    if (tid < NCdim) {
        float a = b_n1[tid];
        #pragma unroll 4
        for (int k = 0; k < NCdim; k++) a += s_h[k] * W_n1[k*NCdim + tid];
        s_n[tid] = a;
    }
    __syncthreads();
    if (tid < NCdim) {
        float a = b_no1[tid];
        #pragma unroll 4
        for (int k = 0; k < NCdim; k++) a += s_h[k] * W_no1[k*NCdim + tid];
        s_t[tid] = a;
    }
    __syncthreads();

    if (tid < 2*OCdim) {
        const int which = tid >> 6;
        const int o = tid & 63;
        const float* src = s_n + which*OCdim;
        float a = 0.f;
        #pragma unroll 4
        for (int k = 0; k < OCdim; k++) a += src[k] * W_f1[k*OCdim + o];
        size_t off = (size_t)(b*Ndim + i)*OCdim + o;
        if (which == 0) { g_q1[off] = a; g_n1[off] = s_n[o]; }
        else            { g_q2[off] = a; g_n2[off] = s_n[OCdim + o]; }
    }

    if (tid < 32) {
        float s = s_t[tid] + s_t[tid+32] + s_t[tid+64] + s_t[tid+96];
        #pragma unroll
        for (int o = 16; o; o >>= 1) s += __shfl_down_sync(0xffffffffu, s, o);
        if (tid == 0) s_stat[0] = s * (1.f/NCdim);
    }
    __syncthreads();
    const float mean = s_stat[0];
    if (tid < 32) {
        float s = 0.f;
        #pragma unroll
        for (int r = 0; r < 4; r++) { float d = s_t[tid + 32*r] - mean; s += d*d; }
        #pragma unroll
        for (int o = 16; o; o >>= 1) s += __shfl_down_sync(0xffffffffu, s, o);
        if (tid == 0) s_stat[1] = rsqrtf(s * (1.f/NCdim) + 1e-5f);
    }
    __syncthreads();
    if (tid < NCdim)
        s_v[tid] = silu_f((s_t[tid] - mean) * s_stat[1] * g_no[tid] + be_no[tid]);
    __syncthreads();
    if (tid < KNdim) {
        float a = b_no2[tid];
        #pragma unroll 4
        for (int k = 0; k < NCdim; k++) a += s_v[k] * W_no2[k*KNdim + tid];
        out_node[(size_t)(b*Ndim + i)*KNdim + tid] = nm_i ? a : 0.f;
    }
}

// ---------------------------------------------------------------------------
// Kernel 2: edge work, warp-per-pair, NO block barriers in the loop.
// Block = 256 threads = 8 warps. Block (b, r) handles rows (r, 511-r): 513
// unordered pairs, strided across warps. Thread lane owns channels
// (2*lane, 2*lane+1) so all vector accesses are float2/float4.
// ---------------------------------------------------------------------------
__global__ __launch_bounds__(256)
void edge_kernel(const float* __restrict__ edge,
                 const int* __restrict__ block_id,
                 const int* __restrict__ vmask,
                 const float* __restrict__ W_e1, const float* __restrict__ b_e1,
                 const float* __restrict__ b_f1,
                 const float* __restrict__ W_f2, const float* __restrict__ b_f2,
                 const float* __restrict__ W_eo1, const float* __restrict__ b_eo1,
                 const float* __restrict__ g_eo, const float* __restrict__ be_eo,
                 const float* __restrict__ W_eo2, const float* __restrict__ b_eo2,
                 float* __restrict__ out_edge)
{
    const int b = blockIdx.x >> 8;
    const int r = blockIdx.x & 255;
    const int tid  = threadIdx.x;
    const int w    = tid >> 5;
    const int lane = tid & 31;

    __shared__ int           s_bid[Ndim];
    __shared__ unsigned char s_vm[Ndim];
    __shared__ float s_we1[ECdim*OCdim];        // [k][c] row-major, 8KB
    __shared__ float s_wf2[OCdim*OCdim];        // [k][c] row-major, 16KB
    __shared__ float s_weo1T[ECdim*68];         // [c][k] pitch 68, 8.5KB
    __shared__ float s_weo2[ECdim*KEdim];       // [k][o]
    __shared__ float s_beo2[KEdim];
    __shared__ __align__(16) float s_er[EWARPS][2][ECdim];
    __shared__ __align__(16) float s_e1[EWARPS][2][OCdim];
    __shared__ __align__(16) float s_es[EWARPS][OCdim];

    for (int k = tid; k < Ndim; k += 256) {
        s_bid[k] = block_id[b*Ndim + k];
        s_vm[k]  = (vmask[b*Ndim + k] != 0) ? 1 : 0;
    }
    for (int k = tid; k < ECdim*OCdim; k += 256) s_we1[k] = W_e1[k];
    for (int k = tid; k < OCdim*OCdim; k += 256) s_wf2[k] = W_f2[k];
    for (int k = tid; k < OCdim*ECdim; k += 256) {
        int kk = k >> 5, c = k & 31;              // W_eo1[kk][c], kk<64, c<32
        s_weo1T[c*68 + kk] = W_eo1[k];
    }
    for (int k = tid; k < ECdim*KEdim; k += 256) s_weo2[k] = W_eo2[k];
    if (tid < KEdim) s_beo2[tid] = b_eo2[tid];
    __syncthreads();

    // per-lane channel constants (channels 2*lane, 2*lane+1 / out-ch lane)
    const float2 bE1 = ((const float2*)b_e1)[lane];
    const float2 bF1 = ((const float2*)b_f1)[lane];
    const float2 bF2 = ((const float2*)b_f2)[lane];
    const float  beo1v = b_eo1[lane];
    const float  geov  = g_eo[lane];
    const float  beeov = be_eo[lane];

    const int i_a = r, i_b = Ndim - 1 - r;
    const int npa   = Ndim - i_a;
    const int total = npa + (Ndim - i_b);   // 513

    const float2* gn1 = (const float2*)g_n1;
    const float2* gn2 = (const float2*)g_n2;
    const float2* gq1 = (const float2*)g_q1;
    const float2* gq2 = (const float2*)g_q2;

    for (int p = w; p < total; p += EWARPS) {
        int i, j;
        if (p < npa) { i = i_a; j = i_a + p; }
        else         { i = i_b; j = i_b + (p - npa); }

        const int  bii = s_bid[i], bjj = s_bid[j];
        const bool nm2 = (bii >= 0) && (bjj >= 0);
        const bool cij = nm2 && ((bii > bjj) || (bii == bjj && s_vm[i] == 0));
        const bool cji = nm2 && ((bjj > bii) || (bjj == bii && s_vm[j] == 0));
        const float em = (cij || cji) ? 1.f : 0.f;

        // load + mask edge vectors (lane = input channel)
        s_er[w][0][lane] = edge[((size_t)(b*Ndim + i)*Ndim + j)*ECdim + lane] * em;
        s_er[w][1][lane] = edge[((size_t)(b*Ndim + j)*Ndim + i)*ECdim + lane] * em;
        __syncwarp();

        // e1 = er @ W_e1 + b_e1, both directions
        float2 aij = bE1, aji = bE1;
        #pragma unroll
        for (int k4 = 0; k4 < ECdim; k4 += 4) {
            float4 u0 = *(const float4*)&s_er[w][0][k4];
            float4 u1 = *(const float4*)&s_er[w][1][k4];
            float2 w0 = ((const float2*)(s_we1 + (k4+0)*OCdim))[lane];
            float2 w1 = ((const float2*)(s_we1 + (k4+1)*OCdim))[lane];
            float2 w2 = ((const float2*)(s_we1 + (k4+2)*OCdim))[lane];
            float2 w3 = ((const float2*)(s_we1 + (k4+3)*OCdim))[lane];
            aij.x += u0.x*w0.x + u0.y*w1.x + u0.z*w2.x + u0.w*w3.x;
            aij.y += u0.x*w0.y + u0.y*w1.y + u0.z*w2.y + u0.w*w3.y;
            aji.x += u1.x*w0.x + u1.y*w1.x + u1.z*w2.x + u1.w*w3.x;
            aji.y += u1.x*w0.y + u1.y*w1.y + u1.z*w2.y + u1.w*w3.y;
        }
        ((float2*)s_e1[w][0])[lane] = aij;
        ((float2*)s_e1[w][1])[lane] = aji;
        __syncwarp();

        // f2 = silu(e1 @ W_f2 + b_f2), both directions
        float2 fij = bF2, fji = bF2;
        #pragma unroll
        for (int k4 = 0; k4 < OCdim; k4 += 4) {
            float4 u0 = *(const float4*)&s_e1[w][0][k4];
            float4 u1 = *(const float4*)&s_e1[w][1][k4];
            float2 w0 = ((const float2*)(s_wf2 + (k4+0)*OCdim))[lane];
            float2 w1 = ((const float2*)(s_wf2 + (k4+1)*OCdim))[lane];
            float2 w2 = ((const float2*)(s_wf2 + (k4+2)*OCdim))[lane];
            float2 w3 = ((const float2*)(s_wf2 + (k4+3)*OCdim))[lane];
            fij.x += u0.x*w0.x + u0.y*w1.x + u0.z*w2.x + u0.w*w3.x;
            fij.y += u0.x*w0.y + u0.y*w1.y + u0.z*w2.y + u0.w*w3.y;
            fji.x += u1.x*w0.x + u1.y*w1.x + u1.z*w2.x + u1.w*w3.x;
            fji.y += u1.x*w0.y + u1.y*w1.y + u1.z*w2.y + u1.w*w3.y;
        }
        fij = silu2(fij);
        fji = silu2(fji);

        // node-pair terms (float2 per lane)
        const size_t offi = (size_t)(b*Ndim + i)*(OCdim/2) + lane;
        const size_t offj = (size_t)(b*Ndim + j)*(OCdim/2) + lane;
        const float2 n1i = gn1[offi], n1j = gn1[offj];
        const float2 n2i = gn2[offi], n2j = gn2[offj];
        const float2 q1i = gq1[offi], q1j = gq1[offj];
        const float2 q2i = gq2[offi], q2j = gq2[offj];

        float2 f1ij = silu2(make_float2(q1j.x + q2i.x + bF1.x, q1j.y + q2i.y + bF1.y));
        float2 f1ji = silu2(make_float2(q1i.x + q2j.x + bF1.x, q1i.y + q2j.y + bF1.y));
        float2 Eij = silu2(make_float2(n1j.x + n2i.x + aij.x + f1ij.x*fij.x,
                                       n1j.y + n2i.y + aij.y + f1ij.y*fij.y));
        float2 Eji = silu2(make_float2(n1i.x + n2j.x + aji.x + f1ji.x*fji.x,
                                       n1i.y + n2j.y + aji.y + f1ji.y*fji.y));
        ((float2*)s_es[w])[lane] = make_float2((Eij.x + Eji.x)*em, (Eij.y + Eji.y)*em);
        __syncwarp();

        // u = es @ W_eo1 + b_eo1 : lane owns output channel `lane`
        float u = beo1v;
        #pragma unroll
        for (int k4 = 0; k4 < OCdim; k4 += 4) {
            float4 e4 = *(const float4*)&s_es[w][k4];
            float4 w4 = *(const float4*)&s_weo1T[lane*68 + k4];
            u += e4.x*w4.x + e4.y*w4.y + e4.z*w4.z + e4.w*w4.w;
        }

        // LayerNorm over 32 lanes + silu
        float m = u;
        #pragma unroll
        for (int o2 = 16; o2; o2 >>= 1) m += __shfl_xor_sync(0xffffffffu, m, o2);
        m *= (1.f/32.f);
        const float d = u - m;
        float var = d*d;
        #pragma unroll
        for (int o2 = 16; o2; o2 >>= 1) var += __shfl_xor_sync(0xffffffffu, var, o2);
        var *= (1.f/32.f);
        const float v = silu_f(d * rsqrtf(var + 1e-5f) * geov + beeov);

        // logits = v @ W_eo2 + b_eo2 via 5 warp reductions
        float t0 = v * s_weo2[lane*KEdim + 0];
        float t1 = v * s_weo2[lane*KEdim + 1];
        float t2 = v * s_weo2[lane*KEdim + 2];
        float t3 = v * s_weo2[lane*KEdim + 3];
        float t4 = v * s_weo2[lane*KEdim + 4];
        #pragma unroll
        for (int o2 = 16; o2; o2 >>= 1) {
            t0 += __shfl_xor_sync(0xffffffffu, t0, o2);
            t1 += __shfl_xor_sync(0xffffffffu, t1, o2);
            t2 += __shfl_xor_sync(0xffffffffu, t2, o2);
            t3 += __shfl_xor_sync(0xffffffffu, t3, o2);
            t4 += __shfl_xor_sync(0xffffffffu, t4, o2);
        }
        if (lane < KEdim) {
            float outv = (lane == 0) ? t0 : (lane == 1) ? t1 : (lane == 2) ? t2
                       : (lane == 3) ? t3 : t4;
            outv = (outv + s_beo2[lane]) * em;
            out_edge[((size_t)(b*Ndim + i)*Ndim + j)*KEdim + lane] = outv;
            out_edge[((size_t)(b*Ndim + j)*Ndim + i)*KEdim + lane] = outv;
        }
    }
}

// ---------------------------------------------------------------------------
extern "C" void kernel_launch(void* const* d_in, const int* in_sizes, int n_in,
                              void* d_out, int out_size)
{
    const float* node      = (const float*)d_in[0];
    const float* edge      = (const float*)d_in[1];
    const int*   block_id  = (const int*)d_in[2];
    const int*   vmask     = (const int*)d_in[3];
    const float* W_nt  = (const float*)d_in[4];
    const float* b_nt  = (const float*)d_in[5];
    const float* W_n1  = (const float*)d_in[6];
    const float* b_n1  = (const float*)d_in[7];
    const float* W_e1  = (const float*)d_in[8];
    const float* b_e1  = (const float*)d_in[9];
    const float* W_f1  = (const float*)d_in[10];
    const float* b_f1  = (const float*)d_in[11];
    const float* W_f2  = (const float*)d_in[12];
    const float* b_f2  = (const float*)d_in[13];
    const float* W_no1 = (const float*)d_in[14];
    const float* b_no1 = (const float*)d_in[15];
    const float* g_no  = (const float*)d_in[16];
    const float* be_no = (const float*)d_in[17];
    const float* W_no2 = (const float*)d_in[18];
    const float* b_no2 = (const float*)d_in[19];
    const float* W_eo1 = (const float*)d_in[20];
    const float* b_eo1 = (const float*)d_in[21];
    const float* g_eo  = (const float*)d_in[22];
    const float* be_eo = (const float*)d_in[23];
    const float* W_eo2 = (const float*)d_in[24];
    const float* b_eo2 = (const float*)d_in[25];

    float* out_node = (float*)d_out;                       // (B,N,KN)
    float* out_edge = (float*)d_out + Bdim*Ndim*KNdim;     // (B,N,N,KE)

    node_kernel<<<Bdim*Ndim, 256>>>(node, edge, block_id, vmask,
                                    W_nt, b_nt, W_n1, b_n1, W_f1,
                                    W_no1, b_no1, g_no, be_no, W_no2, b_no2,
                                    out_node);

    edge_kernel<<<Bdim*256, 256>>>(edge, block_id, vmask,
                                   W_e1, b_e1, b_f1, W_f2, b_f2,
                                   W_eo1, b_eo1, g_eo, be_eo, W_eo2, b_eo2,
                                   out_edge);
}

// round 6
// speedup vs baseline: 3.1325x; 1.2874x over previous
#include <cuda_runtime.h>

#define Bdim 4
#define Ndim 512
#define NCdim 128
#define ECdim 32
#define OCdim 64
#define KNdim 10
#define KEdim 5
#define NIN 192   // 2*EC + NC
#define EWARPS 8

// node-level scratch (no alloc allowed)
__device__ float g_n1[Bdim*Ndim*OCdim];
__device__ float g_n2[Bdim*Ndim*OCdim];
__device__ float g_q1[Bdim*Ndim*OCdim];
__device__ float g_q2[Bdim*Ndim*OCdim];

__device__ __forceinline__ float silu_f(float x) {
    return __fdividef(x, 1.0f + __expf(-x));
}
__device__ __forceinline__ float2 silu2(float2 x) {
    return make_float2(silu_f(x.x), silu_f(x.y));
}

// ---------------------------------------------------------------------------
// Kernel 1: per-node work. One block per (b, i). 256 threads. (unchanged)
// ---------------------------------------------------------------------------
__global__ __launch_bounds__(256)
void node_kernel(const float* __restrict__ node,
                 const float* __restrict__ edge,
                 const int* __restrict__ block_id,
                 const int* __restrict__ vmask,
                 const float* __restrict__ W_nt, const float* __restrict__ b_nt,
                 const float* __restrict__ W_n1, const float* __restrict__ b_n1,
                 const float* __restrict__ W_f1,
                 const float* __restrict__ W_no1, const float* __restrict__ b_no1,
                 const float* __restrict__ g_no, const float* __restrict__ be_no,
                 const float* __restrict__ W_no2, const float* __restrict__ b_no2,
                 float* __restrict__ out_node)
{
    const int bi = blockIdx.x;
    const int b  = bi / Ndim;
    const int i  = bi % Ndim;
    const int tid = threadIdx.x;

    __shared__ int           s_bid[Ndim];
    __shared__ unsigned char s_vm[Ndim];
    __shared__ float s_inp[NIN];
    __shared__ float s_red[8][64];
    __shared__ float s_cnt[2][8];
    __shared__ float s_h[NCdim];
    __shared__ float s_n[NCdim];
    __shared__ float s_t[NCdim];
    __shared__ float s_v[NCdim];
    __shared__ float s_stat[2];

    for (int k = tid; k < Ndim; k += 256) {
        s_bid[k] = block_id[b*Ndim + k];
        s_vm[k]  = (vmask[b*Ndim + k] != 0) ? 1 : 0;
    }
    __syncthreads();

    const int  bii  = s_bid[i];
    const bool nm_i = (bii >= 0);
    const bool vm_i = (s_vm[i] != 0);

    const int c  = tid & 31;
    const int jl = tid >> 5;

    float acc_in = 0.f, acc_out = 0.f, cnt_in = 0.f, cnt_out = 0.f;
    const float* erow = edge + ((size_t)(b*Ndim + i) * Ndim) * ECdim;
    const float* ecol = edge + ((size_t)b*Ndim) * Ndim * ECdim + (size_t)i*ECdim;

    for (int j = jl; j < Ndim; j += 8) {
        int  bj   = s_bid[j];
        bool nm_j = (bj >= 0);
        bool pv   = nm_i && nm_j;
        bool cij  = pv && ((bii > bj) || (bii == bj && !vm_i));
        bool cji  = pv && ((bj > bii) || (bj == bii && (s_vm[j] == 0)));
        if (cij) { acc_in  += erow[(size_t)j*ECdim + c];        cnt_in  += 1.f; }
        if (cji) { acc_out += ecol[(size_t)j*Ndim*ECdim + c];   cnt_out += 1.f; }
    }
    s_red[jl][c]      = acc_in;
    s_red[jl][c + 32] = acc_out;
    if (c == 0) { s_cnt[0][jl] = cnt_in; s_cnt[1][jl] = cnt_out; }
    __syncthreads();

    if (tid < 64) {
        float s = 0.f, cnt = 0.f;
        #pragma unroll
        for (int r = 0; r < 8; r++) { s += s_red[r][tid]; cnt += s_cnt[tid >> 5][r]; }
        s_inp[tid] = s / fmaxf(cnt, 1.f);
    }
    if (tid >= 64 && tid < NIN) {
        float nd = node[(size_t)(b*Ndim + i)*NCdim + (tid - 64)];
        s_inp[tid] = nm_i ? nd : 0.f;
    }
    __syncthreads();

    if (tid < NCdim) {
        float a = b_nt[tid];
        #pragma unroll 4
        for (int k = 0; k < NIN; k++) a += s_inp[k] * W_nt[k*NCdim + tid];
        s_h[tid] = nm_i ? silu_f(a) : 0.f;
    }
    __syncthreads();

    if (tid < NCdim) {
        float a = b_n1[tid];
        #pragma unroll 4
        for (int k = 0; k < NCdim; k++) a += s_h[k] * W_n1[k*NCdim + tid];
        s_n[tid] = a;
    }
    __syncthreads();
    if (tid < NCdim) {
        float a = b_no1[tid];
        #pragma unroll 4
        for (int k = 0; k < NCdim; k++) a += s_h[k] * W_no1[k*NCdim + tid];
        s_t[tid] = a;
    }
    __syncthreads();

    if (tid < 2*OCdim) {
        const int which = tid >> 6;
        const int o = tid & 63;
        const float* src = s_n + which*OCdim;
        float a = 0.f;
        #pragma unroll 4
        for (int k = 0; k < OCdim; k++) a += src[k] * W_f1[k*OCdim + o];
        size_t off = (size_t)(b*Ndim + i)*OCdim + o;
        if (which == 0) { g_q1[off] = a; g_n1[off] = s_n[o]; }
        else            { g_q2[off] = a; g_n2[off] = s_n[OCdim + o]; }
    }

    if (tid < 32) {
        float s = s_t[tid] + s_t[tid+32] + s_t[tid+64] + s_t[tid+96];
        #pragma unroll
        for (int o = 16; o; o >>= 1) s += __shfl_down_sync(0xffffffffu, s, o);
        if (tid == 0) s_stat[0] = s * (1.f/NCdim);
    }
    __syncthreads();
    const float mean = s_stat[0];
    if (tid < 32) {
        float s = 0.f;
        #pragma unroll
        for (int r = 0; r < 4; r++) { float d = s_t[tid + 32*r] - mean; s += d*d; }
        #pragma unroll
        for (int o = 16; o; o >>= 1) s += __shfl_down_sync(0xffffffffu, s, o);
        if (tid == 0) s_stat[1] = rsqrtf(s * (1.f/NCdim) + 1e-5f);
    }
    __syncthreads();
    if (tid < NCdim)
        s_v[tid] = silu_f((s_t[tid] - mean) * s_stat[1] * g_no[tid] + be_no[tid]);
    __syncthreads();
    if (tid < KNdim) {
        float a = b_no2[tid];
        #pragma unroll 4
        for (int k = 0; k < NCdim; k++) a += s_v[k] * W_no2[k*KNdim + tid];
        out_node[(size_t)(b*Ndim + i)*KNdim + tid] = nm_i ? a : 0.f;
    }
}

// ---------------------------------------------------------------------------
// Kernel 2: edge work, warp-synchronous, 4 pairs (8 directions) per warp
// iteration so weight LDS is amortized 4x. Dynamic smem ~74KB.
// ---------------------------------------------------------------------------
// dynamic smem layout (bytes from base):
//   0      : s_key   [512] int (bid*2+vm)
//   2048   : sw_e1   [32*64] f         (row-major [k][c])
//   10240  : sw_f2   [64*64] f         (row-major [k][c])
//   26624  : sw_eo1T [32*68] f         ([c][k], pitch 68)
//   35328  : sw_eo2T [8*36]  f         ([ch][k], pitch 36, rows 5..7 zero)
//   36480  : per-warp region, 4736 B each:
//            m_er [8][32], m_e1 [8][64], m_es [4][68], m_v [4][36]
#define SM_KEY    0
#define SM_WE1    2048
#define SM_WF2    10240
#define SM_WEO1T  26624
#define SM_WEO2T  35328
#define SM_WARP   36480
#define SM_PERW   4736
#define SM_TOTAL  (SM_WARP + EWARPS*SM_PERW)   // 74368
#define ES_PITCH  68

__global__ __launch_bounds__(256)
void edge_kernel(const float* __restrict__ edge,
                 const int* __restrict__ block_id,
                 const int* __restrict__ vmask,
                 const float* __restrict__ W_e1, const float* __restrict__ b_e1,
                 const float* __restrict__ b_f1,
                 const float* __restrict__ W_f2, const float* __restrict__ b_f2,
                 const float* __restrict__ W_eo1, const float* __restrict__ b_eo1,
                 const float* __restrict__ g_eo, const float* __restrict__ be_eo,
                 const float* __restrict__ W_eo2, const float* __restrict__ b_eo2,
                 float* __restrict__ out_edge)
{
    extern __shared__ char dsm[];
    const int b = blockIdx.x >> 8;
    const int r = blockIdx.x & 255;
    const int tid  = threadIdx.x;
    const int w    = tid >> 5;
    const int lane = tid & 31;

    int*   s_key    = (int*)(dsm + SM_KEY);
    float* sw_e1    = (float*)(dsm + SM_WE1);
    float* sw_f2    = (float*)(dsm + SM_WF2);
    float* sw_eo1T  = (float*)(dsm + SM_WEO1T);
    float* sw_eo2T  = (float*)(dsm + SM_WEO2T);
    float* m_er = (float*)(dsm + SM_WARP + w*SM_PERW);   // [8][32]
    float* m_e1 = m_er + 256;                            // [8][64]
    float* m_es = m_e1 + 512;                            // [4][ES_PITCH]
    float* m_v  = m_es + 4*ES_PITCH;                     // [4][36]

    for (int k = tid; k < Ndim; k += 256)
        s_key[k] = block_id[b*Ndim + k]*2 + ((vmask[b*Ndim + k] != 0) ? 1 : 0);
    for (int k = tid; k < ECdim*OCdim; k += 256) sw_e1[k] = W_e1[k];
    for (int k = tid; k < OCdim*OCdim; k += 256) sw_f2[k] = W_f2[k];
    for (int k = tid; k < OCdim*ECdim; k += 256) {
        int kk = k >> 5, c = k & 31;               // W_eo1[kk][c]
        sw_eo1T[c*68 + kk] = W_eo1[k];
    }
    for (int k = tid; k < 8*36; k += 256) {
        int ch = k / 36, kk = k % 36;
        sw_eo2T[k] = (ch < KEdim && kk < ECdim) ? W_eo2[kk*KEdim + ch] : 0.f;
    }
    __syncthreads();

    // per-lane constants
    const float2 bE1 = ((const float2*)b_e1)[lane];
    const float2 bF1 = ((const float2*)b_f1)[lane];
    const float2 bF2 = ((const float2*)b_f2)[lane];
    const float  beo1v = b_eo1[lane];
    const float  geov  = g_eo[lane];
    const float  beeov = be_eo[lane];
    const int    ch2   = lane & 7;                 // eo2 role
    const float  beo2v = (ch2 < KEdim) ? b_eo2[ch2] : 0.f;

    const int i_a = r, i_b = Ndim - 1 - r;
    const int npa   = Ndim - i_a;
    const int total = Ndim + 1;   // 513

    const float2* gn1 = (const float2*)g_n1;
    const float2* gn2 = (const float2*)g_n2;
    const float2* gq1 = (const float2*)g_q1;
    const float2* gq2 = (const float2*)g_q2;

    // i-side node vectors in registers
    const size_t oia = (size_t)(b*Ndim + i_a)*(OCdim/2) + lane;
    const size_t oib = (size_t)(b*Ndim + i_b)*(OCdim/2) + lane;
    const float2 n1ia = gn1[oia], n2ia = gn2[oia], q1ia = gq1[oia], q2ia = gq2[oia];
    const float2 n1ib = gn1[oib], n2ib = gn2[oib], q1ib = gq1[oib], q2ib = gq2[oib];

    for (int base = w*4; base < total; base += EWARPS*4) {
        int ii[4], jj[4];
        float em[4];
        bool act[4], isA[4];
        #pragma unroll
        for (int u = 0; u < 4; u++) {
            int p = base + u;
            act[u] = (p < total);
            int pc = act[u] ? p : 0;
            bool a_ = pc < npa;
            isA[u] = a_;
            ii[u] = a_ ? i_a : i_b;
            jj[u] = a_ ? (i_a + pc) : (i_b + (pc - npa));
            int ki = s_key[ii[u]], kj = s_key[jj[u]];
            int bi_ = ki >> 1, bj_ = kj >> 1;
            bool nm2 = (bi_ >= 0) && (bj_ >= 0);
            bool cij = (bi_ > bj_) || (bi_ == bj_ && !(ki & 1));
            bool cji = (bj_ > bi_) || (bj_ == bi_ && !(kj & 1));
            em[u] = (nm2 && (cij || cji)) ? 1.f : 0.f;
        }

        // load masked edge rows: slot 2u = (i,j), 2u+1 = (j,i)
        #pragma unroll
        for (int u = 0; u < 4; u++) {
            m_er[(2*u  )*32 + lane] = edge[((size_t)(b*Ndim + ii[u])*Ndim + jj[u])*ECdim + lane] * em[u];
            m_er[(2*u+1)*32 + lane] = edge[((size_t)(b*Ndim + jj[u])*Ndim + ii[u])*ECdim + lane] * em[u];
        }
        __syncwarp();

        // e1 = er @ W_e1 + b_e1 for 8 directions
        float2 a[8];
        #pragma unroll
        for (int d = 0; d < 8; d++) a[d] = bE1;
        #pragma unroll
        for (int k4 = 0; k4 < ECdim; k4 += 4) {
            float2 w0 = ((const float2*)(sw_e1 + (k4+0)*OCdim))[lane];
            float2 w1 = ((const float2*)(sw_e1 + (k4+1)*OCdim))[lane];
            float2 w2 = ((const float2*)(sw_e1 + (k4+2)*OCdim))[lane];
            float2 w3 = ((const float2*)(sw_e1 + (k4+3)*OCdim))[lane];
            #pragma unroll
            for (int d = 0; d < 8; d++) {
                float4 uq = *(const float4*)&m_er[d*32 + k4];
                a[d].x += uq.x*w0.x + uq.y*w1.x + uq.z*w2.x + uq.w*w3.x;
                a[d].y += uq.x*w0.y + uq.y*w1.y + uq.z*w2.y + uq.w*w3.y;
            }
        }
        #pragma unroll
        for (int d = 0; d < 8; d++) ((float2*)(m_e1 + d*64))[lane] = a[d];
        __syncwarp();

        // f2raw = e1 @ W_f2 + b_f2 for 8 directions
        float2 f[8];
        #pragma unroll
        for (int d = 0; d < 8; d++) f[d] = bF2;
        #pragma unroll
        for (int k4 = 0; k4 < OCdim; k4 += 4) {
            float2 w0 = ((const float2*)(sw_f2 + (k4+0)*OCdim))[lane];
            float2 w1 = ((const float2*)(sw_f2 + (k4+1)*OCdim))[lane];
            float2 w2 = ((const float2*)(sw_f2 + (k4+2)*OCdim))[lane];
            float2 w3 = ((const float2*)(sw_f2 + (k4+3)*OCdim))[lane];
            #pragma unroll
            for (int d = 0; d < 8; d++) {
                float4 uq = *(const float4*)&m_e1[d*64 + k4];
                f[d].x += uq.x*w0.x + uq.y*w1.x + uq.z*w2.x + uq.w*w3.x;
                f[d].y += uq.x*w0.y + uq.y*w1.y + uq.z*w2.y + uq.w*w3.y;
            }
        }

        // combine with node terms -> es
        #pragma unroll
        for (int u = 0; u < 4; u++) {
            const size_t oj = (size_t)(b*Ndim + jj[u])*(OCdim/2) + lane;
            const float2 n1j = gn1[oj], n2j = gn2[oj], q1j = gq1[oj], q2j = gq2[oj];
            const float2 n1i = isA[u] ? n1ia : n1ib;
            const float2 n2i = isA[u] ? n2ia : n2ib;
            const float2 q1i = isA[u] ? q1ia : q1ib;
            const float2 q2i = isA[u] ? q2ia : q2ib;

            float2 f2ij = silu2(f[2*u]);
            float2 f2ji = silu2(f[2*u+1]);
            float2 f1ij = silu2(make_float2(q1j.x + q2i.x + bF1.x, q1j.y + q2i.y + bF1.y));
            float2 f1ji = silu2(make_float2(q1i.x + q2j.x + bF1.x, q1i.y + q2j.y + bF1.y));
            float2 Eij = silu2(make_float2(n1j.x + n2i.x + a[2*u].x   + f1ij.x*f2ij.x,
                                           n1j.y + n2i.y + a[2*u].y   + f1ij.y*f2ij.y));
            float2 Eji = silu2(make_float2(n1i.x + n2j.x + a[2*u+1].x + f1ji.x*f2ji.x,
                                           n1i.y + n2j.y + a[2*u+1].y + f1ji.y*f2ji.y));
            ((float2*)(m_es + u*ES_PITCH))[lane] = make_float2((Eij.x + Eji.x)*em[u],
                                                               (Eij.y + Eji.y)*em[u]);
        }
        __syncwarp();

        // eo1: lane = out channel; 4 pairs share each weight float4
        float uo0 = beo1v, uo1 = beo1v, uo2 = beo1v, uo3 = beo1v;
        #pragma unroll
        for (int k4 = 0; k4 < OCdim; k4 += 4) {
            float4 w4 = *(const float4*)&sw_eo1T[lane*68 + k4];
            float4 e0  = *(const float4*)&m_es[0*ES_PITCH + k4];
            float4 e1v = *(const float4*)&m_es[1*ES_PITCH + k4];
            float4 e2  = *(const float4*)&m_es[2*ES_PITCH + k4];
            float4 e3  = *(const float4*)&m_es[3*ES_PITCH + k4];
            uo0 += e0.x*w4.x + e0.y*w4.y + e0.z*w4.z + e0.w*w4.w;
            uo1 += e1v.x*w4.x + e1v.y*w4.y + e1v.z*w4.z + e1v.w*w4.w;
            uo2 += e2.x*w4.x + e2.y*w4.y + e2.z*w4.z + e2.w*w4.w;
            uo3 += e3.x*w4.x + e3.y*w4.y + e3.z*w4.z + e3.w*w4.w;
        }

        // LayerNorm + silu per pair, store v
        float uos[4] = {uo0, uo1, uo2, uo3};
        #pragma unroll
        for (int u = 0; u < 4; u++) {
            float x = uos[u];
            float m = x;
            #pragma unroll
            for (int o2 = 16; o2; o2 >>= 1) m += __shfl_xor_sync(0xffffffffu, m, o2);
            m *= (1.f/32.f);
            float dd = x - m;
            float var = dd*dd;
            #pragma unroll
            for (int o2 = 16; o2; o2 >>= 1) var += __shfl_xor_sync(0xffffffffu, var, o2);
            var *= (1.f/32.f);
            m_v[u*36 + lane] = silu_f(dd * rsqrtf(var + 1e-5f) * geov + beeov);
        }
        __syncwarp();

        // eo2: lane = (pair u2 = lane>>3, channel ch2 = lane&7); full dot over 32
        {
            const int u2 = lane >> 3;
            float t = 0.f;
            #pragma unroll
            for (int k4 = 0; k4 < ECdim; k4 += 4) {
                float4 vv = *(const float4*)&m_v[u2*36 + k4];
                float4 w4 = *(const float4*)&sw_eo2T[ch2*36 + k4];
                t += vv.x*w4.x + vv.y*w4.y + vv.z*w4.z + vv.w*w4.w;
            }
            // recompute pair identity (avoid dynamic-indexed local arrays)
            int p2 = base + u2;
            bool act2 = (p2 < total);
            int pc2 = act2 ? p2 : 0;
            bool aA = pc2 < npa;
            int i2 = aA ? i_a : i_b;
            int j2 = aA ? (i_a + pc2) : (i_b + (pc2 - npa));
            int ki = s_key[i2], kj = s_key[j2];
            int bi_ = ki >> 1, bj_ = kj >> 1;
            bool nm2 = (bi_ >= 0) && (bj_ >= 0);
            bool cij = (bi_ > bj_) || (bi_ == bj_ && !(ki & 1));
            bool cji = (bj_ > bi_) || (bj_ == bi_ && !(kj & 1));
            float em2 = (nm2 && (cij || cji)) ? 1.f : 0.f;
            if (ch2 < KEdim && act2) {
                float outv = (t + beo2v) * em2;
                out_edge[((size_t)(b*Ndim + i2)*Ndim + j2)*KEdim + ch2] = outv;
                out_edge[((size_t)(b*Ndim + j2)*Ndim + i2)*KEdim + ch2] = outv;
            }
        }
        __syncwarp();
    }
}

// ---------------------------------------------------------------------------
extern "C" void kernel_launch(void* const* d_in, const int* in_sizes, int n_in,
                              void* d_out, int out_size)
{
    const float* node      = (const float*)d_in[0];
    const float* edge      = (const float*)d_in[1];
    const int*   block_id  = (const int*)d_in[2];
    const int*   vmask     = (const int*)d_in[3];
    const float* W_nt  = (const float*)d_in[4];
    const float* b_nt  = (const float*)d_in[5];
    const float* W_n1  = (const float*)d_in[6];
    const float* b_n1  = (const float*)d_in[7];
    const float* W_e1  = (const float*)d_in[8];
    const float* b_e1  = (const float*)d_in[9];
    const float* W_f1  = (const float*)d_in[10];
    const float* b_f1  = (const float*)d_in[11];
    const float* W_f2  = (const float*)d_in[12];
    const float* b_f2  = (const float*)d_in[13];
    const float* W_no1 = (const float*)d_in[14];
    const float* b_no1 = (const float*)d_in[15];
    const float* g_no  = (const float*)d_in[16];
    const float* be_no = (const float*)d_in[17];
    const float* W_no2 = (const float*)d_in[18];
    const float* b_no2 = (const float*)d_in[19];
    const float* W_eo1 = (const float*)d_in[20];
    const float* b_eo1 = (const float*)d_in[21];
    const float* g_eo  = (const float*)d_in[22];
    const float* be_eo = (const float*)d_in[23];
    const float* W_eo2 = (const float*)d_in[24];
    const float* b_eo2 = (const float*)d_in[25];

    float* out_node = (float*)d_out;                       // (B,N,KN)
    float* out_edge = (float*)d_out + Bdim*Ndim*KNdim;     // (B,N,N,KE)

    static int smem_set = 0;
    if (!smem_set) {
        cudaFuncSetAttribute(edge_kernel, cudaFuncAttributeMaxDynamicSharedMemorySize, SM_TOTAL);
        smem_set = 1;
    }

    node_kernel<<<Bdim*Ndim, 256>>>(node, edge, block_id, vmask,
                                    W_nt, b_nt, W_n1, b_n1, W_f1,
                                    W_no1, b_no1, g_no, be_no, W_no2, b_no2,
                                    out_node);

    edge_kernel<<<Bdim*256, 256, SM_TOTAL>>>(edge, block_id, vmask,
                                   W_e1, b_e1, b_f1, W_f2, b_f2,
                                   W_eo1, b_eo1, g_eo, be_eo, W_eo2, b_eo2,
                                   out_edge);
}

// round 7
// speedup vs baseline: 3.2348x; 1.0327x over previous
#include <cuda_runtime.h>
#include <cuda_fp16.h>
#include <stdint.h>

#define Bdim 4
#define Ndim 512
#define NCdim 128
#define ECdim 32
#define OCdim 64
#define KNdim 10
#define KEdim 5
#define NIN 192   // 2*EC + NC
#define EWARPS 8

// node-level scratch (no alloc allowed)
__device__ float g_n1[Bdim*Ndim*OCdim];
__device__ float g_n2[Bdim*Ndim*OCdim];
__device__ float g_q1[Bdim*Ndim*OCdim];
__device__ float g_q2[Bdim*Ndim*OCdim];

__device__ __forceinline__ float silu_f(float x) {
    return __fdividef(x, 1.0f + __expf(-x));
}

__device__ __forceinline__ void mma16816(float& c0, float& c1, float& c2, float& c3,
                                         uint32_t a0, uint32_t a1, uint32_t a2, uint32_t a3,
                                         uint32_t b0, uint32_t b1) {
    asm volatile("mma.sync.aligned.m16n8k16.row.col.f32.f16.f16.f32 "
                 "{%0,%1,%2,%3},{%4,%5,%6,%7},{%8,%9},{%0,%1,%2,%3};\n"
                 : "+f"(c0), "+f"(c1), "+f"(c2), "+f"(c3)
                 : "r"(a0), "r"(a1), "r"(a2), "r"(a3), "r"(b0), "r"(b1));
}

// split (x,y) into hi/lo half2 pairs (packed u32, .x = low half = first elem)
__device__ __forceinline__ void split_h2(float x, float y, uint32_t& hi, uint32_t& lo) {
    __half hx = __float2half_rn(x), hy = __float2half_rn(y);
    __half lx = __float2half_rn(x - __half2float(hx));
    __half ly = __float2half_rn(y - __half2float(hy));
    __half2 h = __halves2half2(hx, hy), l = __halves2half2(lx, ly);
    hi = *(uint32_t*)&h;  lo = *(uint32_t*)&l;
}

// ---------------------------------------------------------------------------
// Kernel 1: per-node work. (unchanged from round 6, passing)
// ---------------------------------------------------------------------------
__global__ __launch_bounds__(256)
void node_kernel(const float* __restrict__ node,
                 const float* __restrict__ edge,
                 const int* __restrict__ block_id,
                 const int* __restrict__ vmask,
                 const float* __restrict__ W_nt, const float* __restrict__ b_nt,
                 const float* __restrict__ W_n1, const float* __restrict__ b_n1,
                 const float* __restrict__ W_f1,
                 const float* __restrict__ W_no1, const float* __restrict__ b_no1,
                 const float* __restrict__ g_no, const float* __restrict__ be_no,
                 const float* __restrict__ W_no2, const float* __restrict__ b_no2,
                 float* __restrict__ out_node)
{
    const int bi = blockIdx.x;
    const int b  = bi / Ndim;
    const int i  = bi % Ndim;
    const int tid = threadIdx.x;

    __shared__ int           s_bid[Ndim];
    __shared__ unsigned char s_vm[Ndim];
    __shared__ float s_inp[NIN];
    __shared__ float s_red[8][64];
    __shared__ float s_cnt[2][8];
    __shared__ float s_h[NCdim];
    __shared__ float s_n[NCdim];
    __shared__ float s_t[NCdim];
    __shared__ float s_v[NCdim];
    __shared__ float s_stat[2];

    for (int k = tid; k < Ndim; k += 256) {
        s_bid[k] = block_id[b*Ndim + k];
        s_vm[k]  = (vmask[b*Ndim + k] != 0) ? 1 : 0;
    }
    __syncthreads();

    const int  bii  = s_bid[i];
    const bool nm_i = (bii >= 0);
    const bool vm_i = (s_vm[i] != 0);

    const int c  = tid & 31;
    const int jl = tid >> 5;

    float acc_in = 0.f, acc_out = 0.f, cnt_in = 0.f, cnt_out = 0.f;
    const float* erow = edge + ((size_t)(b*Ndim + i) * Ndim) * ECdim;
    const float* ecol = edge + ((size_t)b*Ndim) * Ndim * ECdim + (size_t)i*ECdim;

    for (int j = jl; j < Ndim; j += 8) {
        int  bj   = s_bid[j];
        bool nm_j = (bj >= 0);
        bool pv   = nm_i && nm_j;
        bool cij  = pv && ((bii > bj) || (bii == bj && !vm_i));
        bool cji  = pv && ((bj > bii) || (bj == bii && (s_vm[j] == 0)));
        if (cij) { acc_in  += erow[(size_t)j*ECdim + c];        cnt_in  += 1.f; }
        if (cji) { acc_out += ecol[(size_t)j*Ndim*ECdim + c];   cnt_out += 1.f; }
    }
    s_red[jl][c]      = acc_in;
    s_red[jl][c + 32] = acc_out;
    if (c == 0) { s_cnt[0][jl] = cnt_in; s_cnt[1][jl] = cnt_out; }
    __syncthreads();

    if (tid < 64) {
        float s = 0.f, cnt = 0.f;
        #pragma unroll
        for (int r = 0; r < 8; r++) { s += s_red[r][tid]; cnt += s_cnt[tid >> 5][r]; }
        s_inp[tid] = s / fmaxf(cnt, 1.f);
    }
    if (tid >= 64 && tid < NIN) {
        float nd = node[(size_t)(b*Ndim + i)*NCdim + (tid - 64)];
        s_inp[tid] = nm_i ? nd : 0.f;
    }
    __syncthreads();

    if (tid < NCdim) {
        float a = b_nt[tid];
        #pragma unroll 4
        for (int k = 0; k < NIN; k++) a += s_inp[k] * W_nt[k*NCdim + tid];
        s_h[tid] = nm_i ? silu_f(a) : 0.f;
    }
    __syncthreads();

    if (tid < NCdim) {
        float a = b_n1[tid];
        #pragma unroll 4
        for (int k = 0; k < NCdim; k++) a += s_h[k] * W_n1[k*NCdim + tid];
        s_n[tid] = a;
    }
    __syncthreads();
    if (tid < NCdim) {
        float a = b_no1[tid];
        #pragma unroll 4
        for (int k = 0; k < NCdim; k++) a += s_h[k] * W_no1[k*NCdim + tid];
        s_t[tid] = a;
    }
    __syncthreads();

    if (tid < 2*OCdim) {
        const int which = tid >> 6;
        const int o = tid & 63;
        const float* src = s_n + which*OCdim;
        float a = 0.f;
        #pragma unroll 4
        for (int k = 0; k < OCdim; k++) a += src[k] * W_f1[k*OCdim + o];
        size_t off = (size_t)(b*Ndim + i)*OCdim + o;
        if (which == 0) { g_q1[off] = a; g_n1[off] = s_n[o]; }
        else            { g_q2[off] = a; g_n2[off] = s_n[OCdim + o]; }
    }

    if (tid < 32) {
        float s = s_t[tid] + s_t[tid+32] + s_t[tid+64] + s_t[tid+96];
        #pragma unroll
        for (int o = 16; o; o >>= 1) s += __shfl_down_sync(0xffffffffu, s, o);
        if (tid == 0) s_stat[0] = s * (1.f/NCdim);
    }
    __syncthreads();
    const float mean = s_stat[0];
    if (tid < 32) {
        float s = 0.f;
        #pragma unroll
        for (int r = 0; r < 4; r++) { float d = s_t[tid + 32*r] - mean; s += d*d; }
        #pragma unroll
        for (int o = 16; o; o >>= 1) s += __shfl_down_sync(0xffffffffu, s, o);
        if (tid == 0) s_stat[1] = rsqrtf(s * (1.f/NCdim) + 1e-5f);
    }
    __syncthreads();
    if (tid < NCdim)
        s_v[tid] = silu_f((s_t[tid] - mean) * s_stat[1] * g_no[tid] + be_no[tid]);
    __syncthreads();
    if (tid < KNdim) {
        float a = b_no2[tid];
        #pragma unroll 4
        for (int k = 0; k < NCdim; k++) a += s_v[k] * W_no2[k*KNdim + tid];
        out_node[(size_t)(b*Ndim + i)*KNdim + tid] = nm_i ? a : 0.f;
    }
}

// ---------------------------------------------------------------------------
// Kernel 2: edge work. Warp = 8 pairs = 16 directions per iteration, using
// compensated-fp16 mma.sync.m16n8k16 for e1 (k=32) and f2 (k=64).
// Rows 0-7 of the m16 tile = (i,j) dirs, rows 8-15 = (j,i): symmetrization is
// thread-local in the C fragment. eo1/LN/eo2 stay scalar (round-6 proven).
// ---------------------------------------------------------------------------
// dynamic smem byte offsets
#define SM_KEY     0         // 512 int
#define SM_BE1B    2048      // 64 f  (b_e1)
#define SM_BF2B    2304      // 64 f  (b_f2)
#define SM_BF1     2560      // 64 f  (b_f1)
#define SM_NI      2816      // 8*64 f (n1,n2,q1,q2 for i_a then i_b)
#define SM_BEO1    4864      // 32 f
#define SM_GEO     4992      // 32 f
#define SM_BEEO    5120      // 32 f
#define SM_BEO2    5248      // 8 f
#define SM_EO1T    5296      // 32*68 f
#define SM_EO2T    14000     // 8*36 f
#define SM_BE1H    15152     // 512 uint2 (hi B-frags of W_e1)
#define SM_BE1L    19248     // 512 uint2
#define SM_BF2H    23344     // 1024 uint2
#define SM_BF2L    31536     // 1024 uint2
#define SM_WARP    39728
#define SM_PERW    16160
// per-warp: PQ/er2 union 8448 | e12 4224 | es 2176 | sv 1152 | meta 128
#define SM_TOTAL   (SM_WARP + EWARPS*SM_PERW)   // 169008

__global__ __launch_bounds__(256, 1)
void edge_kernel(const float* __restrict__ edge,
                 const int* __restrict__ block_id,
                 const int* __restrict__ vmask,
                 const float* __restrict__ W_e1, const float* __restrict__ b_e1,
                 const float* __restrict__ b_f1,
                 const float* __restrict__ W_f2, const float* __restrict__ b_f2,
                 const float* __restrict__ W_eo1, const float* __restrict__ b_eo1,
                 const float* __restrict__ g_eo, const float* __restrict__ be_eo,
                 const float* __restrict__ W_eo2, const float* __restrict__ b_eo2,
                 float* __restrict__ out_edge)
{
    extern __shared__ char dsm[];
    const int b = blockIdx.x >> 8;
    const int r = blockIdx.x & 255;
    const int tid  = threadIdx.x;
    const int w    = tid >> 5;
    const int lane = tid & 31;
    const int grp  = lane >> 2;     // 0..7
    const int q    = lane & 3;      // 0..3

    int*   s_key  = (int*)(dsm + SM_KEY);
    float* sbe1b  = (float*)(dsm + SM_BE1B);
    float* sbf2b  = (float*)(dsm + SM_BF2B);
    float* sbF1   = (float*)(dsm + SM_BF1);
    float* s_ni   = (float*)(dsm + SM_NI);
    float* sbeo1  = (float*)(dsm + SM_BEO1);
    float* sgeo   = (float*)(dsm + SM_GEO);
    float* sbeeo  = (float*)(dsm + SM_BEEO);
    float* sbeo2  = (float*)(dsm + SM_BEO2);
    float* sw_eo1T = (float*)(dsm + SM_EO1T);
    float* sw_eo2T = (float*)(dsm + SM_EO2T);
    uint2* be1h   = (uint2*)(dsm + SM_BE1H);
    uint2* be1l   = (uint2*)(dsm + SM_BE1L);
    uint2* bf2h   = (uint2*)(dsm + SM_BF2H);
    uint2* bf2l   = (uint2*)(dsm + SM_BF2L);

    char*  wbase = dsm + SM_WARP + w*SM_PERW;
    float* PQ    = (float*)wbase;          // [16][132] (P,Q interleaved per ch)
    uint2* er2   = (uint2*)wbase;          // [d*17 + c2] (hi,lo) h2 — union w/ PQ
    uint2* e12   = (uint2*)(wbase + 8448); // [row*33 + c2]
    float* es    = (float*)(wbase + 12672);// [8][68]
    float* sv    = (float*)(wbase + 14848);// [8][36]
    int*   smi   = (int*)(wbase + 16000);
    int*   smj   = smi + 8;
    float* sem   = (float*)(smi + 16);
    int*   sact  = smi + 24;

    const int i_a = r, i_b = Ndim - 1 - r;

    // ---- block init ----
    for (int k = tid; k < Ndim; k += 256)
        s_key[k] = block_id[b*Ndim + k]*2 + ((vmask[b*Ndim + k] != 0) ? 1 : 0);
    if (tid < 64)  sbe1b[tid] = b_e1[tid];
    if (tid >= 64 && tid < 128)  sbf2b[tid-64] = b_f2[tid-64];
    if (tid >= 128 && tid < 192) sbF1[tid-128] = b_f1[tid-128];
    if (tid >= 192 && tid < 224) sbeo1[tid-192] = b_eo1[tid-192];
    if (tid >= 224 && tid < 256) sgeo[tid-224] = g_eo[tid-224];
    if (tid < 32)  sbeeo[tid] = be_eo[tid];
    if (tid >= 32 && tid < 40) sbeo2[tid-32] = b_eo2[tid-32];
    // node vectors for the block's two i-rows
    for (int k = tid; k < 512; k += 256) {
        int v = k >> 6, ch = k & 63;
        int irow = (v < 4) ? i_a : i_b;
        const float* src = (v % 4 == 0) ? g_n1 : (v % 4 == 1) ? g_n2 : (v % 4 == 2) ? g_q1 : g_q2;
        s_ni[k] = src[(size_t)(b*Ndim + irow)*OCdim + ch];
    }
    for (int k = tid; k < OCdim*32; k += 256) {
        int kk = k >> 5, c = k & 31;
        sw_eo1T[c*68 + kk] = W_eo1[k];
    }
    for (int k = tid; k < 8*36; k += 256) {
        int ch = k / 36, kk = k % 36;
        sw_eo2T[k] = (ch < KEdim && kk < ECdim) ? W_eo2[kk*KEdim + ch] : 0.f;
    }
    // B-fragment pre-swizzle for W_e1 (k=32 -> 2 ksteps)
    for (int e = tid; e < 512; e += 256) {
        int lane_ = e & 31, nt = (e >> 5) & 7, ks = e >> 8;
        int q_ = lane_ & 3, g_ = lane_ >> 2;
        int k0 = ks*16 + 2*q_;
        int n  = nt*8 + g_;
        uint32_t h0, l0, h1, l1;
        split_h2(W_e1[k0*OCdim + n],     W_e1[(k0+1)*OCdim + n], h0, l0);  // b0
        split_h2(W_e1[(k0+8)*OCdim + n], W_e1[(k0+9)*OCdim + n], h1, l1);  // b1
        be1h[e] = make_uint2(h0, h1);
        be1l[e] = make_uint2(l0, l1);
    }
    // W_f2 (k=64 -> 4 ksteps)
    for (int e = tid; e < 1024; e += 256) {
        int lane_ = e & 31, nt = (e >> 5) & 7, ks = e >> 8;
        int q_ = lane_ & 3, g_ = lane_ >> 2;
        int k0 = ks*16 + 2*q_;
        int n  = nt*8 + g_;
        uint32_t h0, l0, h1, l1;
        split_h2(W_f2[k0*OCdim + n],     W_f2[(k0+1)*OCdim + n], h0, l0);
        split_h2(W_f2[(k0+8)*OCdim + n], W_f2[(k0+9)*OCdim + n], h1, l1);
        bf2h[e] = make_uint2(h0, h1);
        bf2l[e] = make_uint2(l0, l1);
    }
    __syncthreads();

    const float beo1v = sbeo1[lane];
    const float geov  = sgeo[lane];
    const float beeov = sbeeo[lane];

    const int npa   = Ndim - i_a;
    const int total = Ndim + 1;   // 513

    for (int base = w*8; base < total; base += EWARPS*8) {
        // ---- pair metadata ----
        if (lane < 8) {
            int p = base + lane;
            int act = (p < total) ? 1 : 0;
            int pc = act ? p : 0;
            bool aA = pc < npa;
            int i2 = aA ? i_a : i_b;
            int j2 = aA ? (i_a + pc) : (i_b + (pc - npa));
            int ki = s_key[i2], kj = s_key[j2];
            int bi_ = ki >> 1, bj_ = kj >> 1;
            bool nm2 = (bi_ >= 0) && (bj_ >= 0);
            bool cij = (bi_ > bj_) || (bi_ == bj_ && !(ki & 1));
            bool cji = (bj_ > bi_) || (bj_ == bi_ && !(kj & 1));
            smi[lane] = i2; smj[lane] = j2;
            sem[lane] = (nm2 && (cij || cji)) ? 1.f : 0.f;
            sact[lane] = act;
        }
        __syncwarp();

        // ---- load edge rows (16 dirs), mask, split to hi/lo halves ----
        {
            const int d = lane >> 1, half = lane & 1, pr = d & 7;
            const int X = (d < 8) ? smi[pr] : smj[pr];
            const int Y = (d < 8) ? smj[pr] : smi[pr];
            const float emv = sem[pr];
            const float4* src = (const float4*)(edge + ((size_t)(b*Ndim + X)*Ndim + Y)*ECdim + half*16);
            #pragma unroll
            for (int c4 = 0; c4 < 4; c4++) {
                float4 v = src[c4];
                v.x *= emv; v.y *= emv; v.z *= emv; v.w *= emv;
                uint32_t hi, lo;
                split_h2(v.x, v.y, hi, lo);
                er2[d*17 + half*8 + c4*2]     = make_uint2(hi, lo);
                split_h2(v.z, v.w, hi, lo);
                er2[d*17 + half*8 + c4*2 + 1] = make_uint2(hi, lo);
            }
        }
        __syncwarp();

        // ---- e1 = er @ W_e1 + b_e1 (compensated fp16 MMA, k=32) ----
        float cE[8][4];
        #pragma unroll
        for (int nt = 0; nt < 8; nt++) {
            float2 bb = *(const float2*)&sbe1b[nt*8 + 2*q];
            cE[nt][0] = bb.x; cE[nt][1] = bb.y; cE[nt][2] = bb.x; cE[nt][3] = bb.y;
        }
        #pragma unroll
        for (int ks = 0; ks < 2; ks++) {
            uint2 A0 = er2[grp*17 + ks*8 + q];
            uint2 A1 = er2[(grp+8)*17 + ks*8 + q];
            uint2 A2 = er2[grp*17 + ks*8 + q + 4];
            uint2 A3 = er2[(grp+8)*17 + ks*8 + q + 4];
            #pragma unroll
            for (int nt = 0; nt < 8; nt++) {
                uint2 Bh = be1h[(ks*8 + nt)*32 + lane];
                uint2 Bl = be1l[(ks*8 + nt)*32 + lane];
                mma16816(cE[nt][0], cE[nt][1], cE[nt][2], cE[nt][3],
                         A0.x, A1.x, A2.x, A3.x, Bh.x, Bh.y);
                mma16816(cE[nt][0], cE[nt][1], cE[nt][2], cE[nt][3],
                         A0.y, A1.y, A2.y, A3.y, Bh.x, Bh.y);
                mma16816(cE[nt][0], cE[nt][1], cE[nt][2], cE[nt][3],
                         A0.x, A1.x, A2.x, A3.x, Bl.x, Bl.y);
            }
        }
        // store e1 (hi/lo) for f2's A-fragments
        #pragma unroll
        for (int nt = 0; nt < 8; nt++) {
            uint32_t hi, lo;
            split_h2(cE[nt][0], cE[nt][1], hi, lo);
            e12[grp*33 + nt*4 + q] = make_uint2(hi, lo);
            split_h2(cE[nt][2], cE[nt][3], hi, lo);
            e12[(grp+8)*33 + nt*4 + q] = make_uint2(hi, lo);
        }
        __syncwarp();

        // ---- build P/Q per direction (overwrites er2 region) ----
        {
            const int pr = lane >> 2;
            const int chb = (lane & 3) * 16;
            const int j = smj[pr];
            const bool aA = (smi[pr] == i_a);
            const size_t jo = (size_t)(b*Ndim + j)*OCdim + chb;
            const int vb = aA ? 0 : 4;
            #pragma unroll
            for (int c4 = 0; c4 < 4; c4++) {
                float4 n1j = *(const float4*)(g_n1 + jo + c4*4);
                float4 n2j = *(const float4*)(g_n2 + jo + c4*4);
                float4 q1j = *(const float4*)(g_q1 + jo + c4*4);
                float4 q2j = *(const float4*)(g_q2 + jo + c4*4);
                float4 n1i = *(const float4*)&s_ni[(vb+0)*64 + chb + c4*4];
                float4 n2i = *(const float4*)&s_ni[(vb+1)*64 + chb + c4*4];
                float4 q1i = *(const float4*)&s_ni[(vb+2)*64 + chb + c4*4];
                float4 q2i = *(const float4*)&s_ni[(vb+3)*64 + chb + c4*4];
                float4 bf  = *(const float4*)&sbF1[chb + c4*4];
                int ch0 = chb + c4*4;
                // dir pr = (i,j): P = n1j + n2i, Q = silu(q1j + q2i + bF1)
                float4 o;
                o.x = n1j.x + n2i.x;  o.y = silu_f(q1j.x + q2i.x + bf.x);
                o.z = n1j.y + n2i.y;  o.w = silu_f(q1j.y + q2i.y + bf.y);
                *(float4*)&PQ[pr*132 + ch0*2] = o;
                o.x = n1j.z + n2i.z;  o.y = silu_f(q1j.z + q2i.z + bf.z);
                o.z = n1j.w + n2i.w;  o.w = silu_f(q1j.w + q2i.w + bf.w);
                *(float4*)&PQ[pr*132 + ch0*2 + 4] = o;
                // dir pr+8 = (j,i): P = n1i + n2j, Q = silu(q1i + q2j + bF1)
                o.x = n1i.x + n2j.x;  o.y = silu_f(q1i.x + q2j.x + bf.x);
                o.z = n1i.y + n2j.y;  o.w = silu_f(q1i.y + q2j.y + bf.y);
                *(float4*)&PQ[(pr+8)*132 + ch0*2] = o;
                o.x = n1i.z + n2j.z;  o.y = silu_f(q1i.z + q2j.z + bf.z);
                o.z = n1i.w + n2j.w;  o.w = silu_f(q1i.w + q2j.w + bf.w);
                *(float4*)&PQ[(pr+8)*132 + ch0*2 + 4] = o;
            }
        }
        __syncwarp();

        // ---- f2raw = e1 @ W_f2 + b_f2 (compensated fp16 MMA, k=64) ----
        float cF[8][4];
        #pragma unroll
        for (int nt = 0; nt < 8; nt++) {
            float2 bb = *(const float2*)&sbf2b[nt*8 + 2*q];
            cF[nt][0] = bb.x; cF[nt][1] = bb.y; cF[nt][2] = bb.x; cF[nt][3] = bb.y;
        }
        #pragma unroll
        for (int ks = 0; ks < 4; ks++) {
            uint2 A0 = e12[grp*33 + ks*8 + q];
            uint2 A1 = e12[(grp+8)*33 + ks*8 + q];
            uint2 A2 = e12[grp*33 + ks*8 + q + 4];
            uint2 A3 = e12[(grp+8)*33 + ks*8 + q + 4];
            #pragma unroll
            for (int nt = 0; nt < 8; nt++) {
                uint2 Bh = bf2h[(ks*8 + nt)*32 + lane];
                uint2 Bl = bf2l[(ks*8 + nt)*32 + lane];
                mma16816(cF[nt][0], cF[nt][1], cF[nt][2], cF[nt][3],
                         A0.x, A1.x, A2.x, A3.x, Bh.x, Bh.y);
                mma16816(cF[nt][0], cF[nt][1], cF[nt][2], cF[nt][3],
                         A0.y, A1.y, A2.y, A3.y, Bh.x, Bh.y);
                mma16816(cF[nt][0], cF[nt][1], cF[nt][2], cF[nt][3],
                         A0.x, A1.x, A2.x, A3.x, Bl.x, Bl.y);
            }
        }

        // ---- combine: E = silu(P + a + Q*silu(f2)); es = (E_ij + E_ji)*em ----
        {
            const float emv = sem[grp];
            #pragma unroll
            for (int nt = 0; nt < 8; nt++) {
                const int ch0 = nt*8 + 2*q;
                float4 pq0 = *(const float4*)&PQ[grp*132 + ch0*2];
                float4 pq1 = *(const float4*)&PQ[(grp+8)*132 + ch0*2];
                float E00 = silu_f(pq0.x + cE[nt][0] + pq0.y * silu_f(cF[nt][0]));
                float E01 = silu_f(pq0.z + cE[nt][1] + pq0.w * silu_f(cF[nt][1]));
                float E10 = silu_f(pq1.x + cE[nt][2] + pq1.y * silu_f(cF[nt][2]));
                float E11 = silu_f(pq1.z + cE[nt][3] + pq1.w * silu_f(cF[nt][3]));
                float2 o = make_float2((E00 + E10)*emv, (E01 + E11)*emv);
                *(float2*)&es[grp*68 + ch0] = o;
            }
        }
        __syncwarp();

        // ---- eo1: u = es @ W_eo1 + b_eo1 (lane = out channel, 8 pairs) ----
        float u[8];
        #pragma unroll
        for (int pr = 0; pr < 8; pr++) u[pr] = beo1v;
        #pragma unroll
        for (int k4 = 0; k4 < 16; k4++) {
            float4 w4 = *(const float4*)&sw_eo1T[lane*68 + k4*4];
            #pragma unroll
            for (int pr = 0; pr < 8; pr++) {
                float4 e4 = *(const float4*)&es[pr*68 + k4*4];
                u[pr] += e4.x*w4.x + e4.y*w4.y + e4.z*w4.z + e4.w*w4.w;
            }
        }
        // ---- LayerNorm(32) + silu per pair ----
        #pragma unroll
        for (int pr = 0; pr < 8; pr++) {
            float m = u[pr];
            #pragma unroll
            for (int o2 = 16; o2; o2 >>= 1) m += __shfl_xor_sync(0xffffffffu, m, o2);
            m *= (1.f/32.f);
            float dd = u[pr] - m;
            float var = dd*dd;
            #pragma unroll
            for (int o2 = 16; o2; o2 >>= 1) var += __shfl_xor_sync(0xffffffffu, var, o2);
            var *= (1.f/32.f);
            sv[pr*36 + lane] = silu_f(dd * rsqrtf(var + 1e-5f) * geov + beeov);
        }
        __syncwarp();

        // ---- eo2 + write (two halves of 4 pairs) ----
        #pragma unroll
        for (int h = 0; h < 2; h++) {
            const int pr  = h*4 + (lane >> 3);
            const int ch2 = lane & 7;
            float t = 0.f;
            #pragma unroll
            for (int k4 = 0; k4 < 8; k4++) {
                float4 vv = *(const float4*)&sv[pr*36 + k4*4];
                float4 w4 = *(const float4*)&sw_eo2T[ch2*36 + k4*4];
                t += vv.x*w4.x + vv.y*w4.y + vv.z*w4.z + vv.w*w4.w;
            }
            if (ch2 < KEdim && sact[pr]) {
                const int i2 = smi[pr], j2 = smj[pr];
                float outv = (t + sbeo2[ch2]) * sem[pr];
                out_edge[((size_t)(b*Ndim + i2)*Ndim + j2)*KEdim + ch2] = outv;
                out_edge[((size_t)(b*Ndim + j2)*Ndim + i2)*KEdim + ch2] = outv;
            }
        }
        __syncwarp();
    }
}

// ---------------------------------------------------------------------------
extern "C" void kernel_launch(void* const* d_in, const int* in_sizes, int n_in,
                              void* d_out, int out_size)
{
    const float* node      = (const float*)d_in[0];
    const float* edge      = (const float*)d_in[1];
    const int*   block_id  = (const int*)d_in[2];
    const int*   vmask     = (const int*)d_in[3];
    const float* W_nt  = (const float*)d_in[4];
    const float* b_nt  = (const float*)d_in[5];
    const float* W_n1  = (const float*)d_in[6];
    const float* b_n1  = (const float*)d_in[7];
    const float* W_e1  = (const float*)d_in[8];
    const float* b_e1  = (const float*)d_in[9];
    const float* W_f1  = (const float*)d_in[10];
    const float* b_f1  = (const float*)d_in[11];
    const float* W_f2  = (const float*)d_in[12];
    const float* b_f2  = (const float*)d_in[13];
    const float* W_no1 = (const float*)d_in[14];
    const float* b_no1 = (const float*)d_in[15];
    const float* g_no  = (const float*)d_in[16];
    const float* be_no = (const float*)d_in[17];
    const float* W_no2 = (const float*)d_in[18];
    const float* b_no2 = (const float*)d_in[19];
    const float* W_eo1 = (const float*)d_in[20];
    const float* b_eo1 = (const float*)d_in[21];
    const float* g_eo  = (const float*)d_in[22];
    const float* be_eo = (const float*)d_in[23];
    const float* W_eo2 = (const float*)d_in[24];
    const float* b_eo2 = (const float*)d_in[25];

    float* out_node = (float*)d_out;                       // (B,N,KN)
    float* out_edge = (float*)d_out + Bdim*Ndim*KNdim;     // (B,N,N,KE)

    static int smem_set = 0;
    if (!smem_set) {
        cudaFuncSetAttribute(edge_kernel, cudaFuncAttributeMaxDynamicSharedMemorySize, SM_TOTAL);
        smem_set = 1;
    }

    node_kernel<<<Bdim*Ndim, 256>>>(node, edge, block_id, vmask,
                                    W_nt, b_nt, W_n1, b_n1, W_f1,
                                    W_no1, b_no1, g_no, be_no, W_no2, b_no2,
                                    out_node);

    edge_kernel<<<Bdim*256, 256, SM_TOTAL>>>(edge, block_id, vmask,
                                   W_e1, b_e1, b_f1, W_f2, b_f2,
                                   W_eo1, b_eo1, g_eo, be_eo, W_eo2, b_eo2,
                                   out_edge);
}

// round 8
// speedup vs baseline: 5.2806x; 1.6324x over previous
#include <cuda_runtime.h>
#include <cuda_fp16.h>
#include <stdint.h>

#define Bdim 4
#define Ndim 512
#define NCdim 128
#define ECdim 32
#define OCdim 64
#define KNdim 10
#define KEdim 5
#define NIN 192   // 2*EC + NC
#define EWARPS 8

// packed per-node vectors: {n1, n2, q1, q2} per channel (float4-interleaved)
__device__ float g_pk[Bdim*Ndim*OCdim*4];

__device__ __forceinline__ float silu_f(float x) {
    return __fdividef(x, 1.0f + __expf(-x));
}

__device__ __forceinline__ void mma16816(float& c0, float& c1, float& c2, float& c3,
                                         uint32_t a0, uint32_t a1, uint32_t a2, uint32_t a3,
                                         uint32_t b0, uint32_t b1) {
    asm volatile("mma.sync.aligned.m16n8k16.row.col.f32.f16.f16.f32 "
                 "{%0,%1,%2,%3},{%4,%5,%6,%7},{%8,%9},{%0,%1,%2,%3};\n"
                 : "+f"(c0), "+f"(c1), "+f"(c2), "+f"(c3)
                 : "r"(a0), "r"(a1), "r"(a2), "r"(a3), "r"(b0), "r"(b1));
}

// split (x,y) into hi/lo half2 (packed u32; .x = low half = first elem)
__device__ __forceinline__ void split_h2(float x, float y, uint32_t& hi, uint32_t& lo) {
    __half hx = __float2half_rn(x), hy = __float2half_rn(y);
    __half lx = __float2half_rn(x - __half2float(hx));
    __half ly = __float2half_rn(y - __half2float(hy));
    __half2 h = __halves2half2(hx, hy), l = __halves2half2(lx, ly);
    hi = *(uint32_t*)&h;  lo = *(uint32_t*)&l;
}

__device__ __forceinline__ float2 unpack_sum(uint32_t h, uint32_t l) {
    float2 fh = __half22float2(*(__half2*)&h);
    float2 fl = __half22float2(*(__half2*)&l);
    return make_float2(fh.x + fl.x, fh.y + fl.y);
}

// ---------------------------------------------------------------------------
// Kernel 1: per-node work (same math as round 6, writes packed g_pk).
// ---------------------------------------------------------------------------
__global__ __launch_bounds__(256)
void node_kernel(const float* __restrict__ node,
                 const float* __restrict__ edge,
                 const int* __restrict__ block_id,
                 const int* __restrict__ vmask,
                 const float* __restrict__ W_nt, const float* __restrict__ b_nt,
                 const float* __restrict__ W_n1, const float* __restrict__ b_n1,
                 const float* __restrict__ W_f1,
                 const float* __restrict__ W_no1, const float* __restrict__ b_no1,
                 const float* __restrict__ g_no, const float* __restrict__ be_no,
                 const float* __restrict__ W_no2, const float* __restrict__ b_no2,
                 float* __restrict__ out_node)
{
    const int bi = blockIdx.x;
    const int b  = bi / Ndim;
    const int i  = bi % Ndim;
    const int tid = threadIdx.x;

    __shared__ int           s_bid[Ndim];
    __shared__ unsigned char s_vm[Ndim];
    __shared__ float s_inp[NIN];
    __shared__ float s_red[8][64];
    __shared__ float s_cnt[2][8];
    __shared__ float s_h[NCdim];
    __shared__ float s_n[NCdim];
    __shared__ float s_t[NCdim];
    __shared__ float s_v[NCdim];
    __shared__ float s_stat[2];

    for (int k = tid; k < Ndim; k += 256) {
        s_bid[k] = block_id[b*Ndim + k];
        s_vm[k]  = (vmask[b*Ndim + k] != 0) ? 1 : 0;
    }
    __syncthreads();

    const int  bii  = s_bid[i];
    const bool nm_i = (bii >= 0);
    const bool vm_i = (s_vm[i] != 0);

    const int c  = tid & 31;
    const int jl = tid >> 5;

    float acc_in = 0.f, acc_out = 0.f, cnt_in = 0.f, cnt_out = 0.f;
    const float* erow = edge + ((size_t)(b*Ndim + i) * Ndim) * ECdim;
    const float* ecol = edge + ((size_t)b*Ndim) * Ndim * ECdim + (size_t)i*ECdim;

    for (int j = jl; j < Ndim; j += 8) {
        int  bj   = s_bid[j];
        bool nm_j = (bj >= 0);
        bool pv   = nm_i && nm_j;
        bool cij  = pv && ((bii > bj) || (bii == bj && !vm_i));
        bool cji  = pv && ((bj > bii) || (bj == bii && (s_vm[j] == 0)));
        if (cij) { acc_in  += erow[(size_t)j*ECdim + c];        cnt_in  += 1.f; }
        if (cji) { acc_out += ecol[(size_t)j*Ndim*ECdim + c];   cnt_out += 1.f; }
    }
    s_red[jl][c]      = acc_in;
    s_red[jl][c + 32] = acc_out;
    if (c == 0) { s_cnt[0][jl] = cnt_in; s_cnt[1][jl] = cnt_out; }
    __syncthreads();

    if (tid < 64) {
        float s = 0.f, cnt = 0.f;
        #pragma unroll
        for (int r = 0; r < 8; r++) { s += s_red[r][tid]; cnt += s_cnt[tid >> 5][r]; }
        s_inp[tid] = s / fmaxf(cnt, 1.f);
    }
    if (tid >= 64 && tid < NIN) {
        float nd = node[(size_t)(b*Ndim + i)*NCdim + (tid - 64)];
        s_inp[tid] = nm_i ? nd : 0.f;
    }
    __syncthreads();

    if (tid < NCdim) {
        float a = b_nt[tid];
        #pragma unroll 4
        for (int k = 0; k < NIN; k++) a += s_inp[k] * W_nt[k*NCdim + tid];
        s_h[tid] = nm_i ? silu_f(a) : 0.f;
    }
    __syncthreads();

    if (tid < NCdim) {
        float a = b_n1[tid];
        #pragma unroll 4
        for (int k = 0; k < NCdim; k++) a += s_h[k] * W_n1[k*NCdim + tid];
        s_n[tid] = a;
    }
    __syncthreads();
    if (tid < NCdim) {
        float a = b_no1[tid];
        #pragma unroll 4
        for (int k = 0; k < NCdim; k++) a += s_h[k] * W_no1[k*NCdim + tid];
        s_t[tid] = a;
    }
    __syncthreads();

    if (tid < 2*OCdim) {
        const int which = tid >> 6;
        const int o = tid & 63;
        const float* src = s_n + which*OCdim;
        float a = 0.f;
        #pragma unroll 4
        for (int k = 0; k < OCdim; k++) a += src[k] * W_f1[k*OCdim + o];
        size_t base = ((size_t)(b*Ndim + i)*OCdim + o)*4;
        if (which == 0) { g_pk[base + 0] = s_n[o];         g_pk[base + 2] = a; }
        else            { g_pk[base + 1] = s_n[OCdim + o]; g_pk[base + 3] = a; }
    }

    if (tid < 32) {
        float s = s_t[tid] + s_t[tid+32] + s_t[tid+64] + s_t[tid+96];
        #pragma unroll
        for (int o = 16; o; o >>= 1) s += __shfl_down_sync(0xffffffffu, s, o);
        if (tid == 0) s_stat[0] = s * (1.f/NCdim);
    }
    __syncthreads();
    const float mean = s_stat[0];
    if (tid < 32) {
        float s = 0.f;
        #pragma unroll
        for (int r = 0; r < 4; r++) { float d = s_t[tid + 32*r] - mean; s += d*d; }
        #pragma unroll
        for (int o = 16; o; o >>= 1) s += __shfl_down_sync(0xffffffffu, s, o);
        if (tid == 0) s_stat[1] = rsqrtf(s * (1.f/NCdim) + 1e-5f);
    }
    __syncthreads();
    if (tid < NCdim)
        s_v[tid] = silu_f((s_t[tid] - mean) * s_stat[1] * g_no[tid] + be_no[tid]);
    __syncthreads();
    if (tid < KNdim) {
        float a = b_no2[tid];
        #pragma unroll 4
        for (int k = 0; k < NCdim; k++) a += s_v[k] * W_no2[k*KNdim + tid];
        out_node[(size_t)(b*Ndim + i)*KNdim + tid] = nm_i ? a : 0.f;
    }
}

// ---------------------------------------------------------------------------
// Kernel 2: edge work. Warp = 8 pairs (16 dirs) per iteration. All MMA
// fragments built in registers (thread-local e1->f2 repack); no er/e1/PQ
// smem staging. smem ~67KB, __launch_bounds__(256,2) for 2 CTAs/SM.
// ---------------------------------------------------------------------------
#define SM_KEY     0         // 512 int
#define SM_BE1B    2048      // 64 f
#define SM_BF2B    2304      // 64 f
#define SM_BF1     2560      // 64 f
#define SM_NIPK    2816      // 128 float4 ({n1,n2,q1,q2} for i_a row0, i_b row1)
#define SM_BEO1    4864      // 32 f
#define SM_GEO     4992      // 32 f
#define SM_BEEO    5120      // 32 f
#define SM_BEO2    5248      // 8 f (+pad)
#define SM_EO1T    5296      // 32*68 f
#define SM_EO2T    14000     // 8*36 f
#define SM_BE1H    15152     // 512 uint2
#define SM_BE1L    19248     // 512 uint2
#define SM_BF2H    23344     // 1024 uint2
#define SM_BF2L    31536     // 1024 uint2
#define SM_WARP    39728
#define SM_PERW    3456      // es [8][68]f 2176 | sv [8][36]f 1152 | meta 128
#define SM_TOTAL   (SM_WARP + EWARPS*SM_PERW)   // 67376

__global__ __launch_bounds__(256, 2)
void edge_kernel(const float* __restrict__ edge,
                 const int* __restrict__ block_id,
                 const int* __restrict__ vmask,
                 const float* __restrict__ W_e1, const float* __restrict__ b_e1,
                 const float* __restrict__ b_f1,
                 const float* __restrict__ W_f2, const float* __restrict__ b_f2,
                 const float* __restrict__ W_eo1, const float* __restrict__ b_eo1,
                 const float* __restrict__ g_eo, const float* __restrict__ be_eo,
                 const float* __restrict__ W_eo2, const float* __restrict__ b_eo2,
                 float* __restrict__ out_edge)
{
    extern __shared__ char dsm[];
    const int b = blockIdx.x >> 8;
    const int r = blockIdx.x & 255;
    const int tid  = threadIdx.x;
    const int w    = tid >> 5;
    const int lane = tid & 31;
    const int grp  = lane >> 2;     // 0..7 = pair slot
    const int q    = lane & 3;      // 0..3

    int*    s_key  = (int*)(dsm + SM_KEY);
    float*  sbe1b  = (float*)(dsm + SM_BE1B);
    float*  sbf2b  = (float*)(dsm + SM_BF2B);
    float*  sbF1   = (float*)(dsm + SM_BF1);
    float4* s_nipk = (float4*)(dsm + SM_NIPK);
    float*  sbeo1  = (float*)(dsm + SM_BEO1);
    float*  sgeo   = (float*)(dsm + SM_GEO);
    float*  sbeeo  = (float*)(dsm + SM_BEEO);
    float*  sbeo2  = (float*)(dsm + SM_BEO2);
    float*  sw_eo1T = (float*)(dsm + SM_EO1T);
    float*  sw_eo2T = (float*)(dsm + SM_EO2T);
    uint2*  be1h   = (uint2*)(dsm + SM_BE1H);
    uint2*  be1l   = (uint2*)(dsm + SM_BE1L);
    uint2*  bf2h   = (uint2*)(dsm + SM_BF2H);
    uint2*  bf2l   = (uint2*)(dsm + SM_BF2L);

    char*  wbase = dsm + SM_WARP + w*SM_PERW;
    float* es    = (float*)wbase;            // [8][68]
    float* sv    = (float*)(wbase + 2176);   // [8][36]
    int*   smi   = (int*)(wbase + 3328);     // [8]
    int*   smj   = smi + 8;
    float* sem   = (float*)(smi + 16);
    int*   sact  = smi + 24;

    const int i_a = r, i_b = Ndim - 1 - r;

    // ---- block init ----
    for (int k = tid; k < Ndim; k += 256)
        s_key[k] = block_id[b*Ndim + k]*2 + ((vmask[b*Ndim + k] != 0) ? 1 : 0);
    if (tid < 64)  sbe1b[tid] = b_e1[tid];
    if (tid >= 64 && tid < 128)  sbf2b[tid-64] = b_f2[tid-64];
    if (tid >= 128 && tid < 192) sbF1[tid-128] = b_f1[tid-128];
    if (tid >= 192 && tid < 224) sbeo1[tid-192] = b_eo1[tid-192];
    if (tid >= 224 && tid < 256) sgeo[tid-224] = g_eo[tid-224];
    if (tid < 32)  sbeeo[tid] = be_eo[tid];
    if (tid >= 32 && tid < 40) sbeo2[tid-32] = b_eo2[tid-32];
    // packed i-side node vectors for rows i_a (slot 0) and i_b (slot 1)
    if (tid >= 40 && tid < 168) {
        int k = tid - 40;              // 0..127
        int row = k >> 6, ch = k & 63;
        int irow = row ? i_b : i_a;
        s_nipk[k] = *(const float4*)&g_pk[((size_t)(b*Ndim + irow)*OCdim + ch)*4];
    }
    for (int k = tid; k < OCdim*32; k += 256) {
        int kk = k >> 5, c = k & 31;
        sw_eo1T[c*68 + kk] = W_eo1[k];
    }
    for (int k = tid; k < 8*36; k += 256) {
        int ch = k / 36, kk = k % 36;
        sw_eo2T[k] = (ch < KEdim && kk < ECdim) ? W_eo2[kk*KEdim + ch] : 0.f;
    }
    // B-fragment pre-swizzle W_e1 (k=32: 2 ksteps)
    for (int e = tid; e < 512; e += 256) {
        int lane_ = e & 31, nt = (e >> 5) & 7, ks = e >> 8;
        int q_ = lane_ & 3, g_ = lane_ >> 2;
        int k0 = ks*16 + 2*q_;
        int n  = nt*8 + g_;
        uint32_t h0, l0, h1, l1;
        split_h2(W_e1[k0*OCdim + n],     W_e1[(k0+1)*OCdim + n], h0, l0);
        split_h2(W_e1[(k0+8)*OCdim + n], W_e1[(k0+9)*OCdim + n], h1, l1);
        be1h[e] = make_uint2(h0, h1);
        be1l[e] = make_uint2(l0, l1);
    }
    // W_f2 (k=64: 4 ksteps)
    for (int e = tid; e < 1024; e += 256) {
        int lane_ = e & 31, nt = (e >> 5) & 7, ks = e >> 8;
        int q_ = lane_ & 3, g_ = lane_ >> 2;
        int k0 = ks*16 + 2*q_;
        int n  = nt*8 + g_;
        uint32_t h0, l0, h1, l1;
        split_h2(W_f2[k0*OCdim + n],     W_f2[(k0+1)*OCdim + n], h0, l0);
        split_h2(W_f2[(k0+8)*OCdim + n], W_f2[(k0+9)*OCdim + n], h1, l1);
        bf2h[e] = make_uint2(h0, h1);
        bf2l[e] = make_uint2(l0, l1);
    }
    __syncthreads();

    const float beo1v = sbeo1[lane];
    const float geov  = sgeo[lane];
    const float beeov = sbeeo[lane];

    const int npa   = Ndim - i_a;
    const int total = Ndim + 1;   // 513

    for (int base = w*8; base < total; base += EWARPS*8) {
        // ---- pair metadata ----
        if (lane < 8) {
            int p = base + lane;
            int act = (p < total) ? 1 : 0;
            int pc = act ? p : 0;
            bool aA = pc < npa;
            int i2 = aA ? i_a : i_b;
            int j2 = aA ? (i_a + pc) : (i_b + (pc - npa));
            int ki = s_key[i2], kj = s_key[j2];
            int bi_ = ki >> 1, bj_ = kj >> 1;
            bool nm2 = (bi_ >= 0) && (bj_ >= 0);
            bool cij = (bi_ > bj_) || (bi_ == bj_ && !(ki & 1));
            bool cji = (bj_ > bi_) || (bj_ == bi_ && !(kj & 1));
            smi[lane] = i2; smj[lane] = j2;
            sem[lane] = (nm2 && (cij || cji)) ? 1.f : 0.f;
            sact[lane] = act;
        }
        __syncwarp();

        const int   i2  = smi[grp];
        const int   j2  = smj[grp];
        const float emv = sem[grp];
        const bool  isA = (i2 == i_a);

        // ---- load edge rows directly into A-fragments (registers) ----
        uint32_t aEh[8], aEl[8];
        {
            const float* eij = edge + ((size_t)(b*Ndim + i2)*Ndim + j2)*ECdim;
            const float* eji = edge + ((size_t)(b*Ndim + j2)*Ndim + i2)*ECdim;
            #pragma unroll
            for (int ks = 0; ks < 2; ks++) {
                float2 v0 = *(const float2*)(eij + ks*16 + 2*q);
                float2 v1 = *(const float2*)(eji + ks*16 + 2*q);
                float2 v2 = *(const float2*)(eij + ks*16 + 8 + 2*q);
                float2 v3 = *(const float2*)(eji + ks*16 + 8 + 2*q);
                split_h2(v0.x*emv, v0.y*emv, aEh[ks*4+0], aEl[ks*4+0]);
                split_h2(v1.x*emv, v1.y*emv, aEh[ks*4+1], aEl[ks*4+1]);
                split_h2(v2.x*emv, v2.y*emv, aEh[ks*4+2], aEl[ks*4+2]);
                split_h2(v3.x*emv, v3.y*emv, aEh[ks*4+3], aEl[ks*4+3]);
            }
        }

        // ---- e1 = er @ W_e1 + b_e1 (compensated fp16 MMA, k=32) ----
        float cE[8][4];
        #pragma unroll
        for (int nt = 0; nt < 8; nt++) {
            float2 bb = *(const float2*)&sbe1b[nt*8 + 2*q];
            cE[nt][0] = bb.x; cE[nt][1] = bb.y; cE[nt][2] = bb.x; cE[nt][3] = bb.y;
        }
        #pragma unroll
        for (int ks = 0; ks < 2; ks++) {
            #pragma unroll
            for (int nt = 0; nt < 8; nt++) {
                uint2 Bh = be1h[(ks*8 + nt)*32 + lane];
                uint2 Bl = be1l[(ks*8 + nt)*32 + lane];
                mma16816(cE[nt][0], cE[nt][1], cE[nt][2], cE[nt][3],
                         aEh[ks*4+0], aEh[ks*4+1], aEh[ks*4+2], aEh[ks*4+3], Bh.x, Bh.y);
                mma16816(cE[nt][0], cE[nt][1], cE[nt][2], cE[nt][3],
                         aEl[ks*4+0], aEl[ks*4+1], aEl[ks*4+2], aEl[ks*4+3], Bh.x, Bh.y);
                mma16816(cE[nt][0], cE[nt][1], cE[nt][2], cE[nt][3],
                         aEh[ks*4+0], aEh[ks*4+1], aEh[ks*4+2], aEh[ks*4+3], Bl.x, Bl.y);
            }
        }

        // ---- thread-local repack: e1 C-frag -> f2 A-frags (hi/lo) ----
        uint32_t e1h[16], e1l[16];
        #pragma unroll
        for (int ks = 0; ks < 4; ks++) {
            split_h2(cE[2*ks][0],   cE[2*ks][1],   e1h[ks*4+0], e1l[ks*4+0]);
            split_h2(cE[2*ks][2],   cE[2*ks][3],   e1h[ks*4+1], e1l[ks*4+1]);
            split_h2(cE[2*ks+1][0], cE[2*ks+1][1], e1h[ks*4+2], e1l[ks*4+2]);
            split_h2(cE[2*ks+1][2], cE[2*ks+1][3], e1h[ks*4+3], e1l[ks*4+3]);
        }

        // ---- f2raw = e1 @ W_f2 + b_f2 (compensated fp16 MMA, k=64) ----
        float cF[8][4];
        #pragma unroll
        for (int nt = 0; nt < 8; nt++) {
            float2 bb = *(const float2*)&sbf2b[nt*8 + 2*q];
            cF[nt][0] = bb.x; cF[nt][1] = bb.y; cF[nt][2] = bb.x; cF[nt][3] = bb.y;
        }
        #pragma unroll
        for (int ks = 0; ks < 4; ks++) {
            #pragma unroll
            for (int nt = 0; nt < 8; nt++) {
                uint2 Bh = bf2h[(ks*8 + nt)*32 + lane];
                uint2 Bl = bf2l[(ks*8 + nt)*32 + lane];
                mma16816(cF[nt][0], cF[nt][1], cF[nt][2], cF[nt][3],
                         e1h[ks*4+0], e1h[ks*4+1], e1h[ks*4+2], e1h[ks*4+3], Bh.x, Bh.y);
                mma16816(cF[nt][0], cF[nt][1], cF[nt][2], cF[nt][3],
                         e1l[ks*4+0], e1l[ks*4+1], e1l[ks*4+2], e1l[ks*4+3], Bh.x, Bh.y);
                mma16816(cF[nt][0], cF[nt][1], cF[nt][2], cF[nt][3],
                         e1h[ks*4+0], e1h[ks*4+1], e1h[ks*4+2], e1h[ks*4+3], Bl.x, Bl.y);
            }
        }

        // ---- combine: E = silu(P + e1 + Q*silu(f2)); es = (E_ij+E_ji)*em ----
        {
            const float4* gpk = (const float4*)g_pk;
            const size_t jo = (size_t)(b*Ndim + j2)*OCdim;
            const int    ib = isA ? 0 : 64;
            #pragma unroll
            for (int nt = 0; nt < 8; nt++) {
                const int ch0 = nt*8 + 2*q;
                const int ksi = (nt >> 1)*4 + (nt & 1)*2;
                float2 e1a = unpack_sum(e1h[ksi],   e1l[ksi]);    // row grp   (i,j)
                float2 e1b = unpack_sum(e1h[ksi+1], e1l[ksi+1]);  // row grp+8 (j,i)
                float4 pj0 = gpk[jo + ch0];
                float4 pj1 = gpk[jo + ch0 + 1];
                float4 pi0 = s_nipk[ib + ch0];
                float4 pi1 = s_nipk[ib + ch0 + 1];
                float2 bf  = *(const float2*)&sbF1[ch0];
                float Q00 = silu_f(pj0.z + pi0.w + bf.x);
                float Q01 = silu_f(pj1.z + pi1.w + bf.y);
                float Q10 = silu_f(pi0.z + pj0.w + bf.x);
                float Q11 = silu_f(pi1.z + pj1.w + bf.y);
                float E00 = silu_f(pj0.x + pi0.y + e1a.x + Q00*silu_f(cF[nt][0]));
                float E01 = silu_f(pj1.x + pi1.y + e1a.y + Q01*silu_f(cF[nt][1]));
                float E10 = silu_f(pi0.x + pj0.y + e1b.x + Q10*silu_f(cF[nt][2]));
                float E11 = silu_f(pi1.x + pj1.y + e1b.y + Q11*silu_f(cF[nt][3]));
                *(float2*)&es[grp*68 + ch0] = make_float2((E00+E10)*emv, (E01+E11)*emv);
            }
        }
        __syncwarp();

        // ---- eo1: u = es @ W_eo1 + b_eo1 (lane = out channel, 8 pairs) ----
        float u[8];
        #pragma unroll
        for (int pr = 0; pr < 8; pr++) u[pr] = beo1v;
        #pragma unroll
        for (int k4 = 0; k4 < 16; k4++) {
            float4 w4 = *(const float4*)&sw_eo1T[lane*68 + k4*4];
            #pragma unroll
            for (int pr = 0; pr < 8; pr++) {
                float4 e4 = *(const float4*)&es[pr*68 + k4*4];
                u[pr] += e4.x*w4.x + e4.y*w4.y + e4.z*w4.z + e4.w*w4.w;
            }
        }
        // ---- LayerNorm(32) + silu per pair ----
        #pragma unroll
        for (int pr = 0; pr < 8; pr++) {
            float m = u[pr];
            #pragma unroll
            for (int o2 = 16; o2; o2 >>= 1) m += __shfl_xor_sync(0xffffffffu, m, o2);
            m *= (1.f/32.f);
            float dd = u[pr] - m;
            float var = dd*dd;
            #pragma unroll
            for (int o2 = 16; o2; o2 >>= 1) var += __shfl_xor_sync(0xffffffffu, var, o2);
            var *= (1.f/32.f);
            sv[pr*36 + lane] = silu_f(dd * rsqrtf(var + 1e-5f) * geov + beeov);
        }
        __syncwarp();

        // ---- eo2 + write (two halves of 4 pairs) ----
        #pragma unroll
        for (int h = 0; h < 2; h++) {
            const int pr  = h*4 + (lane >> 3);
            const int ch2 = lane & 7;
            float t = 0.f;
            #pragma unroll
            for (int k4 = 0; k4 < 8; k4++) {
                float4 vv = *(const float4*)&sv[pr*36 + k4*4];
                float4 w4 = *(const float4*)&sw_eo2T[ch2*36 + k4*4];
                t += vv.x*w4.x + vv.y*w4.y + vv.z*w4.z + vv.w*w4.w;
            }
            if (ch2 < KEdim && sact[pr]) {
                const int io = smi[pr], jo2 = smj[pr];
                float outv = (t + sbeo2[ch2]) * sem[pr];
                out_edge[((size_t)(b*Ndim + io)*Ndim + jo2)*KEdim + ch2] = outv;
                out_edge[((size_t)(b*Ndim + jo2)*Ndim + io)*KEdim + ch2] = outv;
            }
        }
        __syncwarp();
    }
}

// ---------------------------------------------------------------------------
extern "C" void kernel_launch(void* const* d_in, const int* in_sizes, int n_in,
                              void* d_out, int out_size)
{
    const float* node      = (const float*)d_in[0];
    const float* edge      = (const float*)d_in[1];
    const int*   block_id  = (const int*)d_in[2];
    const int*   vmask     = (const int*)d_in[3];
    const float* W_nt  = (const float*)d_in[4];
    const float* b_nt  = (const float*)d_in[5];
    const float* W_n1  = (const float*)d_in[6];
    const float* b_n1  = (const float*)d_in[7];
    const float* W_e1  = (const float*)d_in[8];
    const float* b_e1  = (const float*)d_in[9];
    const float* W_f1  = (const float*)d_in[10];
    const float* b_f1  = (const float*)d_in[11];
    const float* W_f2  = (const float*)d_in[12];
    const float* b_f2  = (const float*)d_in[13];
    const float* W_no1 = (const float*)d_in[14];
    const float* b_no1 = (const float*)d_in[15];
    const float* g_no  = (const float*)d_in[16];
    const float* be_no = (const float*)d_in[17];
    const float* W_no2 = (const float*)d_in[18];
    const float* b_no2 = (const float*)d_in[19];
    const float* W_eo1 = (const float*)d_in[20];
    const float* b_eo1 = (const float*)d_in[21];
    const float* g_eo  = (const float*)d_in[22];
    const float* be_eo = (const float*)d_in[23];
    const float* W_eo2 = (const float*)d_in[24];
    const float* b_eo2 = (const float*)d_in[25];

    float* out_node = (float*)d_out;                       // (B,N,KN)
    float* out_edge = (float*)d_out + Bdim*Ndim*KNdim;     // (B,N,N,KE)

    static int smem_set = 0;
    if (!smem_set) {
        cudaFuncSetAttribute(edge_kernel, cudaFuncAttributeMaxDynamicSharedMemorySize, SM_TOTAL);
        smem_set = 1;
    }

    node_kernel<<<Bdim*Ndim, 256>>>(node, edge, block_id, vmask,
                                    W_nt, b_nt, W_n1, b_n1, W_f1,
                                    W_no1, b_no1, g_no, be_no, W_no2, b_no2,
                                    out_node);

    edge_kernel<<<Bdim*256, 256, SM_TOTAL>>>(edge, block_id, vmask,
                                   W_e1, b_e1, b_f1, W_f2, b_f2,
                                   W_eo1, b_eo1, g_eo, be_eo, W_eo2, b_eo2,
                                   out_edge);
}